// round 11
// baseline (speedup 1.0000x reference)
#include <cuda_runtime.h>
#include <cuda_bf16.h>
#include <cstddef>
#include <cstdint>

#define BATCH 64
#define LSEQ 784
#define HDIM 512
#define NSTATE 64
#define NLAYERS 6
#define MT 13            // m-tiles of 64 rows, 13*64 = 832 >= 784
#define KRRN 1024        // reversed-padded kernel length per h

// -------- scratch (no allocations allowed) --------
__device__ float g_h[(size_t)HDIM * LSEQ * BATCH];   // activations, (H,L,B)
__device__ float g_y[(size_t)HDIM * LSEQ * BATCH];   // z = h + conv(h), (H,L,B)
__device__ float g_K[NLAYERS * HDIM * LSEQ];         // conv kernels
__device__ __nv_bfloat16 g_krrhi[(size_t)NLAYERS * HDIM * KRRN];
__device__ __nv_bfloat16 g_krrlo[(size_t)NLAYERS * HDIM * KRRN];
__device__ float g_wr[NLAYERS * HDIM * NSTATE];
__device__ float g_wi[NLAYERS * HDIM * NSTATE];
__device__ float g_cr[NLAYERS * HDIM * NSTATE];
__device__ float g_ci[NLAYERS * HDIM * NSTATE];
__device__ float g_pool[HDIM * BATCH];

// -------- ptx helpers --------
__device__ __forceinline__ uint32_t smaddr(const void* p) {
    return (uint32_t)__cvta_generic_to_shared(p);
}
__device__ __forceinline__ void ldsm4(uint32_t& r0, uint32_t& r1, uint32_t& r2, uint32_t& r3,
                                      uint32_t addr) {
    asm volatile("ldmatrix.sync.aligned.m8n8.x4.shared.b16 {%0,%1,%2,%3}, [%4];"
                 : "=r"(r0), "=r"(r1), "=r"(r2), "=r"(r3) : "r"(addr));
}
__device__ __forceinline__ void mma16816(float* d, uint32_t a0, uint32_t a1, uint32_t a2,
                                         uint32_t a3, uint32_t b0, uint32_t b1) {
    asm volatile("mma.sync.aligned.m16n8k16.row.col.f32.bf16.bf16.f32 "
                 "{%0,%1,%2,%3}, {%4,%5,%6,%7}, {%8,%9}, {%0,%1,%2,%3};"
                 : "+f"(d[0]), "+f"(d[1]), "+f"(d[2]), "+f"(d[3])
                 : "r"(a0), "r"(a1), "r"(a2), "r"(a3), "r"(b0), "r"(b1));
}
// pack two consecutive bf16 from smem into one b32 (lo = first element)
__device__ __forceinline__ uint32_t pk2(const __nv_bfloat16* a, int i) {
    uint32_t lo = *(const uint16_t*)(a + i);
    uint32_t hi = *(const uint16_t*)(a + i + 1);
    return lo | (hi << 16);
}

// -------- precompute discretized SSM params --------
__global__ void precompute_kernel(const float* __restrict__ log_dt,
                                  const float* __restrict__ log_A_real,
                                  const float* __restrict__ A_imag,
                                  const float* __restrict__ C_re,
                                  const float* __restrict__ C_im) {
    int idx = blockIdx.x * blockDim.x + threadIdx.x;
    if (idx >= NLAYERS * HDIM * NSTATE) return;
    int hh = (idx / NSTATE) % HDIM;
    int i = idx / (NSTATE * HDIM);
    float dt = expf(log_dt[i * HDIM + hh]);
    float Ar = -expf(log_A_real[idx]);
    float Ai = A_imag[idx];
    float xr = Ar * dt, xi = Ai * dt;
    float e = expf(xr);
    float wre = e * cosf(xi), wim = e * sinf(xi);
    float em1r = wre - 1.0f, em1i = wim;
    float Cre = C_re[idx], Cim = C_im[idx];
    float tr = Cre * em1r - Cim * em1i;
    float ti = Cre * em1i + Cim * em1r;
    float inv = 1.0f / (Ar * Ar + Ai * Ai);
    g_wr[idx] = wre; g_wi[idx] = wim;
    g_cr[idx] = (tr * Ar + ti * Ai) * inv;
    g_ci[idx] = (ti * Ar - tr * Ai) * inv;
}

// -------- kernel generation: impulse response of the recurrence --------
// grid (HDIM/16, NLAYERS), block 128. 8 lanes per h, 8 states per lane.
__global__ void __launch_bounds__(128) kgen_kernel() {
    __shared__ float shy[16][120];
    int tid = threadIdx.x;
    int warp = tid >> 5, lane = tid & 31;
    int g = lane >> 3, lg = lane & 7;
    int pairLocal = warp * 4 + g;
    int h = blockIdx.x * 16 + pairLocal;
    int layer = blockIdx.y;
    int pbase = (layer * HDIM + h) * NSTATE;
    float swr[8], swi[8], scr[8], sci[8], sre[8], sim[8];
#pragma unroll
    for (int j = 0; j < 8; j++) {
        int n = lg + 8 * j;
        swr[j] = g_wr[pbase + n]; swi[j] = g_wi[pbase + n];
        scr[j] = g_cr[pbase + n]; sci[j] = g_ci[pbase + n];
        sre[j] = 0.0f; sim[j] = 0.0f;
    }
    float* krow = g_K + (size_t)(layer * HDIM + h) * LSEQ;
    for (int c0 = 0; c0 < LSEQ; c0 += 112) {
#pragma unroll 4
        for (int l = 0; l < 112; l++) {
            float uv = (c0 + l == 0) ? 1.0f : 0.0f;
            float acc = 0.0f;
#pragma unroll
            for (int j = 0; j < 8; j++) {
                float nr = fmaf(swr[j], sre[j], fmaf(-swi[j], sim[j], uv));
                float ni = fmaf(swr[j], sim[j], swi[j] * sre[j]);
                sre[j] = nr; sim[j] = ni;
                acc = fmaf(scr[j], nr, acc);
                acc = fmaf(-sci[j], ni, acc);
            }
            acc += __shfl_xor_sync(0xffffffffu, acc, 1, 8);
            acc += __shfl_xor_sync(0xffffffffu, acc, 2, 8);
            acc += __shfl_xor_sync(0xffffffffu, acc, 4, 8);
            if (lg == 0) shy[pairLocal][l] = 2.0f * acc;
        }
        __syncwarp();
#pragma unroll
        for (int k = 0; k < 14; k++)
            krow[c0 + lg + 8 * k] = shy[pairLocal][lg + 8 * k];
        __syncwarp();
    }
}

// -------- build reversed zero-padded bf16 hi/lo kernel: KRR[t] = Kpad[831-t] --------
__global__ void __launch_bounds__(256) krr_kernel() {
    int h = blockIdx.x, layer = blockIdx.y;
    const float* kr = g_K + (size_t)(layer * HDIM + h) * LSEQ;
    __nv_bfloat16* oh = g_krrhi + (size_t)(layer * HDIM + h) * KRRN;
    __nv_bfloat16* ol = g_krrlo + (size_t)(layer * HDIM + h) * KRRN;
    for (int t = threadIdx.x; t < KRRN; t += 256) {
        int d = 831 - t;
        float v = (d >= 0 && d < LSEQ) ? kr[d] : 0.0f;
        __nv_bfloat16 hi = __float2bfloat16(v);
        __nv_bfloat16 lo = __float2bfloat16(v - __bfloat162float(hi));
        oh[t] = hi; ol[t] = lo;
    }
}

// -------- encoder: h[h,l,b] = x[b,l]*enc_w[h] + enc_b[h] --------
__global__ void __launch_bounds__(256) encoder_kernel(const float* __restrict__ x,
                                                      const float* __restrict__ enc_w,
                                                      const float* __restrict__ enc_b) {
    int l = blockIdx.x;
    __shared__ float xs[BATCH];
    if (threadIdx.x < BATCH) xs[threadIdx.x] = x[threadIdx.x * LSEQ + l];
    __syncthreads();
    for (int idx = threadIdx.x; idx < HDIM * BATCH; idx += 256) {
        int h = idx >> 6, b = idx & 63;
        g_h[((size_t)h * LSEQ + l) * BATCH + b] = fmaf(xs[b], enc_w[h], enc_b[h]);
    }
}

// -------- S4 conv as triangular Toeplitz GEMM, bf16-split, fp32 accum --------
// grid = HDIM*MT blocks, 128 threads (4 warps). Each block: h, m-tile of 64 rows,
// all 64 batch cols, k-loop over chunks of 16 up to the diagonal.
__global__ void __launch_bounds__(128) gemm_kernel(int layer, const float* __restrict__ Dvec) {
    __shared__ __align__(16) __nv_bfloat16 Ksm[2][KRRN];         // hi, lo
    __shared__ __align__(16) __nv_bfloat16 Usm[2][2][64][24];    // [buf][plane][n=b][k]
    int tid = threadIdx.x;
    int id = blockIdx.x;
    int mt = id % MT;
    int h = id / MT;
    int m0 = mt * 64;
    int warp = tid >> 5, lane = tid & 31;
    int g = lane >> 2, t2 = (lane & 3) * 2;
    const float* U = g_h + (size_t)h * (LSEQ * BATCH);

    {   // load kernel slice (hi+lo) into smem
        const __nv_bfloat16* kh = g_krrhi + (size_t)(layer * HDIM + h) * KRRN;
        const __nv_bfloat16* kl = g_krrlo + (size_t)(layer * HDIM + h) * KRRN;
        for (int i = tid; i < KRRN; i += 128) { Ksm[0][i] = kh[i]; Ksm[1][i] = kl[i]; }
    }

    int nc = mt * 4 + 4;          // k-chunks of 16 covering k <= m0+63
    int kq = tid >> 3;            // staging: k row 0..15
    int b0s = (tid & 7) * 8;      // staging: 8 consecutive b

    // prefetch + store chunk 0
    float4 pv0, pv1;
    {
        const float4* p = (const float4*)(U + (size_t)kq * BATCH + b0s);
        pv0 = p[0]; pv1 = p[1];   // chunk0 rows always < 784
        float vals[8] = {pv0.x, pv0.y, pv0.z, pv0.w, pv1.x, pv1.y, pv1.z, pv1.w};
#pragma unroll
        for (int i = 0; i < 8; i++) {
            __nv_bfloat16 hi = __float2bfloat16(vals[i]);
            Usm[0][0][b0s + i][kq] = hi;
            Usm[0][1][b0s + i][kq] = __float2bfloat16(vals[i] - __bfloat162float(hi));
        }
    }
    __syncthreads();

    float acc[8][4];
#pragma unroll
    for (int u = 0; u < 8; u++)
#pragma unroll
        for (int c = 0; c < 4; c++) acc[u][c] = 0.0f;

    // ldmatrix lane->address: covers 2 n-units per x4
    int lrow = (lane >> 4) * 8 + (lane & 7);
    int lkoff = ((lane >> 3) & 1) * 8;

    for (int kc = 0; kc < nc; kc++) {
        int buf = kc & 1;
        int has = (kc + 1 < nc);
        float4 nv0, nv1;
        if (has) {
            int kglob = (kc + 1) * 16 + kq;
            if (kglob < LSEQ) {
                const float4* p = (const float4*)(U + (size_t)kglob * BATCH + b0s);
                nv0 = p[0]; nv1 = p[1];
            } else {
                nv0 = make_float4(0.f, 0.f, 0.f, 0.f); nv1 = nv0;
            }
        }
        // A fragments (Toeplitz: a3 == a0)
        int x0 = 831 - m0 - warp * 16 + kc * 16 + t2 - g;
        uint32_t ah0 = pk2(Ksm[0], x0), ah1 = pk2(Ksm[0], x0 - 8), ah2 = pk2(Ksm[0], x0 + 8);
        uint32_t al0 = pk2(Ksm[1], x0), al1 = pk2(Ksm[1], x0 - 8), al2 = pk2(Ksm[1], x0 + 8);
#pragma unroll
        for (int up = 0; up < 4; up++) {
            uint32_t ahh = smaddr(&Usm[buf][0][up * 16 + lrow][lkoff]);
            uint32_t ahl = smaddr(&Usm[buf][1][up * 16 + lrow][lkoff]);
            uint32_t bh0, bh1, bh2, bh3, bl0, bl1, bl2, bl3;
            ldsm4(bh0, bh1, bh2, bh3, ahh);
            ldsm4(bl0, bl1, bl2, bl3, ahl);
            mma16816(acc[2 * up],     ah0, ah1, ah2, ah0, bh0, bh1);
            mma16816(acc[2 * up],     ah0, ah1, ah2, ah0, bl0, bl1);
            mma16816(acc[2 * up],     al0, al1, al2, al0, bh0, bh1);
            mma16816(acc[2 * up + 1], ah0, ah1, ah2, ah0, bh2, bh3);
            mma16816(acc[2 * up + 1], ah0, ah1, ah2, ah0, bl2, bl3);
            mma16816(acc[2 * up + 1], al0, al1, al2, al0, bh2, bh3);
        }
        if (has) {   // store next chunk to other buffer (safe: other buf free)
            float vals[8] = {nv0.x, nv0.y, nv0.z, nv0.w, nv1.x, nv1.y, nv1.z, nv1.w};
            int nb = buf ^ 1;
#pragma unroll
            for (int i = 0; i < 8; i++) {
                __nv_bfloat16 hi = __float2bfloat16(vals[i]);
                Usm[nb][0][b0s + i][kq] = hi;
                Usm[nb][1][b0s + i][kq] = __float2bfloat16(vals[i] - __bfloat162float(hi));
            }
        }
        __syncthreads();
    }

    // epilogue: z = (1+D)*u + conv, into g_y (H,L,B)
    float D1 = 1.0f + Dvec[layer * HDIM + h];
    float* Z = g_y + (size_t)h * (LSEQ * BATCH);
    int R0 = m0 + warp * 16 + g;
    int R1 = R0 + 8;
#pragma unroll
    for (int u = 0; u < 8; u++) {
        int b = u * 8 + t2;
        if (R0 < LSEQ) {
            size_t o = (size_t)R0 * BATCH + b;
            Z[o]     = fmaf(D1, U[o], acc[u][0]);
            Z[o + 1] = fmaf(D1, U[o + 1], acc[u][1]);
        }
        if (R1 < LSEQ) {
            size_t o = (size_t)R1 * BATCH + b;
            Z[o]     = fmaf(D1, U[o], acc[u][2]);
            Z[o + 1] = fmaf(D1, U[o + 1], acc[u][3]);
        }
    }
}

// -------- layernorm over H, (H,L,B) layout --------
// grid (LSEQ, BATCH/16), block 512 = 16 b-lanes x 32 h-threads
__global__ void __launch_bounds__(512) ln_kernel(const float* __restrict__ gamma,
                                                 const float* __restrict__ beta,
                                                 int addY) {
    int l = blockIdx.x;
    int b0 = blockIdx.y * 16;
    int lx = threadIdx.x & 15;
    int hy = threadIdx.x >> 4;
    __shared__ float z[HDIM][16];
    __shared__ float s1s[32][16], s2s[32][16];
    __shared__ float smean[16], srstd[16];
    const float* src = addY ? g_y : g_h;
    float s1 = 0.0f, s2 = 0.0f;
    for (int h = hy; h < HDIM; h += 32) {
        size_t off = ((size_t)h * LSEQ + l) * BATCH + b0 + lx;
        float v = src[off];
        z[h][lx] = v;
        s1 += v; s2 += v * v;
    }
    s1s[hy][lx] = s1; s2s[hy][lx] = s2;
    __syncthreads();
    for (int st = 16; st >= 1; st >>= 1) {
        if (hy < st) { s1s[hy][lx] += s1s[hy + st][lx]; s2s[hy][lx] += s2s[hy + st][lx]; }
        __syncthreads();
    }
    if (hy == 0) {
        float mean = s1s[0][lx] * (1.0f / HDIM);
        float var = s2s[0][lx] * (1.0f / HDIM) - mean * mean;
        smean[lx] = mean;
        srstd[lx] = rsqrtf(var + 1e-5f);
    }
    __syncthreads();
    float mean = smean[lx], rstd = srstd[lx];
    for (int h = hy; h < HDIM; h += 32) {
        size_t off = ((size_t)h * LSEQ + l) * BATCH + b0 + lx;
        g_h[off] = (z[h][lx] - mean) * rstd * gamma[h] + beta[h];
    }
}

// -------- mean-pool over L --------
__global__ void __launch_bounds__(256) pool_kernel() {
    int h = blockIdx.x;
    int b = threadIdx.x & 63, part = threadIdx.x >> 6;
    float s = 0.0f;
    for (int l = part; l < LSEQ; l += 4)
        s += g_h[((size_t)h * LSEQ + l) * BATCH + b];
    __shared__ float red[4][64];
    red[part][b] = s;
    __syncthreads();
    if (part == 0)
        g_pool[h * BATCH + b] = (red[0][b] + red[1][b] + red[2][b] + red[3][b]) * (1.0f / LSEQ);
}

// -------- decode to 10 classes --------
__global__ void __launch_bounds__(256) decode_kernel(const float* __restrict__ dec_w,
                                                     const float* __restrict__ dec_b,
                                                     float* __restrict__ out) {
    int b = blockIdx.x;
    int t = threadIdx.x;
    float acc[10];
#pragma unroll
    for (int k = 0; k < 10; k++) acc[k] = 0.0f;
    for (int h = t; h < HDIM; h += 256) {
        float p = g_pool[h * BATCH + b];
#pragma unroll
        for (int k = 0; k < 10; k++) acc[k] = fmaf(p, dec_w[h * 10 + k], acc[k]);
    }
    __shared__ float red[256];
    for (int k = 0; k < 10; k++) {
        red[t] = acc[k];
        __syncthreads();
        for (int st = 128; st >= 1; st >>= 1) {
            if (t < st) red[t] += red[t + st];
            __syncthreads();
        }
        if (t == 0) out[b * 10 + k] = red[0] + dec_b[k];
        __syncthreads();
    }
}

extern "C" void kernel_launch(void* const* d_in, const int* in_sizes, int n_in,
                              void* d_out, int out_size) {
    const float* x          = (const float*)d_in[0];
    const float* enc_w      = (const float*)d_in[1];
    const float* enc_b      = (const float*)d_in[2];
    const float* log_dt     = (const float*)d_in[3];
    const float* log_A_real = (const float*)d_in[4];
    const float* A_imag     = (const float*)d_in[5];
    const float* C_re       = (const float*)d_in[6];
    const float* C_im       = (const float*)d_in[7];
    const float* Dvec       = (const float*)d_in[8];
    const float* ln_g       = (const float*)d_in[9];
    const float* ln_b       = (const float*)d_in[10];
    const float* fn_g       = (const float*)d_in[11];
    const float* fn_b       = (const float*)d_in[12];
    const float* dec_w      = (const float*)d_in[13];
    const float* dec_b      = (const float*)d_in[14];
    float* out = (float*)d_out;

    int np = NLAYERS * HDIM * NSTATE;
    precompute_kernel<<<(np + 255) / 256, 256>>>(log_dt, log_A_real, A_imag, C_re, C_im);
    kgen_kernel<<<dim3(HDIM / 16, NLAYERS), 128>>>();
    krr_kernel<<<dim3(HDIM, NLAYERS), 256>>>();
    encoder_kernel<<<LSEQ, 256>>>(x, enc_w, enc_b);

    for (int i = 0; i < NLAYERS; i++) {
        gemm_kernel<<<HDIM * MT, 128>>>(i, Dvec);
        ln_kernel<<<dim3(LSEQ, BATCH / 16), 512>>>(ln_g + i * HDIM, ln_b + i * HDIM, 1);
    }
    ln_kernel<<<dim3(LSEQ, BATCH / 16), 512>>>(fn_g, fn_b, 0);
    pool_kernel<<<HDIM, 256>>>();
    decode_kernel<<<BATCH, 256>>>(dec_w, dec_b, out);
}

// round 12
// speedup vs baseline: 1.5944x; 1.5944x over previous
#include <cuda_runtime.h>
#include <cuda_bf16.h>
#include <cstddef>
#include <cstdint>

#define BATCH 64
#define LSEQ 784
#define HDIM 512
#define NSTATE 64
#define NLAYERS 6
#define MT 7             // m-tiles of 128 rows, 7*128 = 896 >= 784
#define REV 895
#define KRRN 1024        // reversed-padded kernel length per h

// -------- scratch (no allocations allowed) --------
__device__ float g_h[(size_t)HDIM * LSEQ * BATCH];   // activations, (H,L,B) fp32
__device__ float g_y[(size_t)HDIM * LSEQ * BATCH];   // z = h + conv(h), (H,L,B)
__device__ __nv_bfloat16 g_ubhi[(size_t)HDIM * LSEQ * BATCH];  // bf16 hi of g_h
__device__ __nv_bfloat16 g_ublo[(size_t)HDIM * LSEQ * BATCH];  // bf16 lo of g_h
__device__ float g_K[NLAYERS * HDIM * LSEQ];         // conv kernels
__device__ __nv_bfloat16 g_krrhi[(size_t)NLAYERS * HDIM * KRRN];
__device__ __nv_bfloat16 g_krrlo[(size_t)NLAYERS * HDIM * KRRN];
__device__ float g_wr[NLAYERS * HDIM * NSTATE];
__device__ float g_wi[NLAYERS * HDIM * NSTATE];
__device__ float g_cr[NLAYERS * HDIM * NSTATE];
__device__ float g_ci[NLAYERS * HDIM * NSTATE];
__device__ float g_pool[HDIM * BATCH];

// -------- ptx helpers --------
__device__ __forceinline__ uint32_t smaddr(const void* p) {
    return (uint32_t)__cvta_generic_to_shared(p);
}
__device__ __forceinline__ void ldsm4t(uint32_t& r0, uint32_t& r1, uint32_t& r2, uint32_t& r3,
                                       uint32_t addr) {
    asm volatile("ldmatrix.sync.aligned.m8n8.x4.trans.shared.b16 {%0,%1,%2,%3}, [%4];"
                 : "=r"(r0), "=r"(r1), "=r"(r2), "=r"(r3) : "r"(addr));
}
__device__ __forceinline__ void mma16816(float* d, uint32_t a0, uint32_t a1, uint32_t a2,
                                         uint32_t a3, uint32_t b0, uint32_t b1) {
    asm volatile("mma.sync.aligned.m16n8k16.row.col.f32.bf16.bf16.f32 "
                 "{%0,%1,%2,%3}, {%4,%5,%6,%7}, {%8,%9}, {%0,%1,%2,%3};"
                 : "+f"(d[0]), "+f"(d[1]), "+f"(d[2]), "+f"(d[3])
                 : "r"(a0), "r"(a1), "r"(a2), "r"(a3), "r"(b0), "r"(b1));
}
__device__ __forceinline__ uint32_t pk2(const __nv_bfloat16* a, int i) {
    uint32_t lo = *(const uint16_t*)(a + i);
    uint32_t hi = *(const uint16_t*)(a + i + 1);
    return lo | (hi << 16);
}
__device__ __forceinline__ void cpasync16(uint32_t dst, const void* src, int sz) {
    asm volatile("cp.async.cg.shared.global [%0], [%1], 16, %2;"
                 :: "r"(dst), "l"(src), "r"(sz));
}

// -------- precompute discretized SSM params --------
__global__ void precompute_kernel(const float* __restrict__ log_dt,
                                  const float* __restrict__ log_A_real,
                                  const float* __restrict__ A_imag,
                                  const float* __restrict__ C_re,
                                  const float* __restrict__ C_im) {
    int idx = blockIdx.x * blockDim.x + threadIdx.x;
    if (idx >= NLAYERS * HDIM * NSTATE) return;
    int hh = (idx / NSTATE) % HDIM;
    int i = idx / (NSTATE * HDIM);
    float dt = expf(log_dt[i * HDIM + hh]);
    float Ar = -expf(log_A_real[idx]);
    float Ai = A_imag[idx];
    float xr = Ar * dt, xi = Ai * dt;
    float e = expf(xr);
    float wre = e * cosf(xi), wim = e * sinf(xi);
    float em1r = wre - 1.0f, em1i = wim;
    float Cre = C_re[idx], Cim = C_im[idx];
    float tr = Cre * em1r - Cim * em1i;
    float ti = Cre * em1i + Cim * em1r;
    float inv = 1.0f / (Ar * Ar + Ai * Ai);
    g_wr[idx] = wre; g_wi[idx] = wim;
    g_cr[idx] = (tr * Ar + ti * Ai) * inv;
    g_ci[idx] = (ti * Ar - tr * Ai) * inv;
}

// -------- kernel generation: impulse response of the recurrence --------
__global__ void __launch_bounds__(128) kgen_kernel() {
    __shared__ float shy[16][120];
    int tid = threadIdx.x;
    int warp = tid >> 5, lane = tid & 31;
    int g = lane >> 3, lg = lane & 7;
    int pairLocal = warp * 4 + g;
    int h = blockIdx.x * 16 + pairLocal;
    int layer = blockIdx.y;
    int pbase = (layer * HDIM + h) * NSTATE;
    float swr[8], swi[8], scr[8], sci[8], sre[8], sim[8];
#pragma unroll
    for (int j = 0; j < 8; j++) {
        int n = lg + 8 * j;
        swr[j] = g_wr[pbase + n]; swi[j] = g_wi[pbase + n];
        scr[j] = g_cr[pbase + n]; sci[j] = g_ci[pbase + n];
        sre[j] = 0.0f; sim[j] = 0.0f;
    }
    float* krow = g_K + (size_t)(layer * HDIM + h) * LSEQ;
    for (int c0 = 0; c0 < LSEQ; c0 += 112) {
#pragma unroll 4
        for (int l = 0; l < 112; l++) {
            float uv = (c0 + l == 0) ? 1.0f : 0.0f;
            float acc = 0.0f;
#pragma unroll
            for (int j = 0; j < 8; j++) {
                float nr = fmaf(swr[j], sre[j], fmaf(-swi[j], sim[j], uv));
                float ni = fmaf(swr[j], sim[j], swi[j] * sre[j]);
                sre[j] = nr; sim[j] = ni;
                acc = fmaf(scr[j], nr, acc);
                acc = fmaf(-sci[j], ni, acc);
            }
            acc += __shfl_xor_sync(0xffffffffu, acc, 1, 8);
            acc += __shfl_xor_sync(0xffffffffu, acc, 2, 8);
            acc += __shfl_xor_sync(0xffffffffu, acc, 4, 8);
            if (lg == 0) shy[pairLocal][l] = 2.0f * acc;
        }
        __syncwarp();
#pragma unroll
        for (int k = 0; k < 14; k++)
            krow[c0 + lg + 8 * k] = shy[pairLocal][lg + 8 * k];
        __syncwarp();
    }
}

// -------- build reversed zero-padded bf16 hi/lo kernel: KRR[t] = Kpad[REV-t] --------
__global__ void __launch_bounds__(256) krr_kernel() {
    int h = blockIdx.x, layer = blockIdx.y;
    const float* kr = g_K + (size_t)(layer * HDIM + h) * LSEQ;
    __nv_bfloat16* oh = g_krrhi + (size_t)(layer * HDIM + h) * KRRN;
    __nv_bfloat16* ol = g_krrlo + (size_t)(layer * HDIM + h) * KRRN;
    for (int t = threadIdx.x; t < KRRN; t += 256) {
        int d = REV - t;
        float v = (d >= 0 && d < LSEQ) ? kr[d] : 0.0f;
        __nv_bfloat16 hi = __float2bfloat16(v);
        __nv_bfloat16 lo = __float2bfloat16(v - __bfloat162float(hi));
        oh[t] = hi; ol[t] = lo;
    }
}

// -------- encoder: h[h,l,b] = x[b,l]*enc_w[h] + enc_b[h], plus bf16 split --------
__global__ void __launch_bounds__(256) encoder_kernel(const float* __restrict__ x,
                                                      const float* __restrict__ enc_w,
                                                      const float* __restrict__ enc_b) {
    int l = blockIdx.x;
    __shared__ float xs[BATCH];
    if (threadIdx.x < BATCH) xs[threadIdx.x] = x[threadIdx.x * LSEQ + l];
    __syncthreads();
    for (int idx = threadIdx.x; idx < HDIM * BATCH; idx += 256) {
        int h = idx >> 6, b = idx & 63;
        size_t off = ((size_t)h * LSEQ + l) * BATCH + b;
        float v = fmaf(xs[b], enc_w[h], enc_b[h]);
        g_h[off] = v;
        __nv_bfloat16 hi = __float2bfloat16(v);
        g_ubhi[off] = hi;
        g_ublo[off] = __float2bfloat16(v - __bfloat162float(hi));
    }
}

// -------- S4 conv as triangular Toeplitz GEMM, bf16-split, fp32 accum --------
// 256 threads / 8 warps. Block: (h, 128-row m-tile). Warp: 16 rows x 64 batch cols.
// B operand staged by cp.async as Usm[k][b] (16x128B), swizzle unit^= (k&7),
// fragments via ldmatrix.x4.trans.
__global__ void __launch_bounds__(256) gemm_kernel(int layer, const float* __restrict__ Dvec) {
    __shared__ __align__(16) __nv_bfloat16 Ksm[2][KRRN];          // hi, lo (4KB)
    __shared__ __align__(16) uint8_t Usm[2][2][16 * 128];         // [buf][plane][k*128 + unit*16] (8KB)
    int tid = threadIdx.x;
    int id = blockIdx.x;
    int mt = id % MT;
    int h = id / MT;
    int m0 = mt * 128;
    int warp = tid >> 5, lane = tid & 31;
    int g = lane >> 2, t2 = (lane & 3) * 2;
    const float* U = g_h + (size_t)h * (LSEQ * BATCH);

    {   // load kernel slice (hi+lo) vectorized
        const uint4* kh4 = (const uint4*)(g_krrhi + (size_t)(layer * HDIM + h) * KRRN);
        const uint4* kl4 = (const uint4*)(g_krrlo + (size_t)(layer * HDIM + h) * KRRN);
        int p = tid >> 7, j = tid & 127;          // 128 uint4 per plane
        ((uint4*)Ksm[p])[j] = p ? kl4[j] : kh4[j];
    }

    // staging assignment: 2 planes x 128 threads; each thread one 16B cp.async per chunk
    const __nv_bfloat16* usrc0 = g_ubhi + (size_t)h * (LSEQ * BATCH);
    const __nv_bfloat16* usrc1 = g_ublo + (size_t)h * (LSEQ * BATCH);
    int sp = tid >> 7;
    const __nv_bfloat16* usrc = sp ? usrc1 : usrc0;
    int si = tid & 127;
    int sk = si >> 3, sj = si & 7;
    uint32_t dstoff = (uint32_t)(sk * 128 + ((sj ^ (sk & 7)) << 4));
    uint32_t dstbase0 = smaddr(&Usm[0][sp][0]) + dstoff;
    uint32_t dstbase1 = smaddr(&Usm[1][sp][0]) + dstoff;

    int nc = mt * 8 + 8;

    // prologue: issue chunk 0
    {
        int kglob = sk;                         // chunk 0, always < LSEQ
        cpasync16(dstbase0, usrc + (size_t)kglob * BATCH + sj * 8, 16);
        asm volatile("cp.async.commit_group;");
    }

    float acc[8][4];
#pragma unroll
    for (int u = 0; u < 8; u++)
#pragma unroll
        for (int c = 0; c < 4; c++) acc[u][c] = 0.0f;

    // ldmatrix.trans lane mapping: lane -> matrix m = lane>>3, row r = lane&7
    int r = lane & 7, mm = lane >> 3;
    int khh = mm & 1, bg = mm >> 1;
    uint32_t rowoff = (uint32_t)((khh * 8 + r) * 128);

    for (int kc = 0; kc < nc; kc++) {
        int buf = kc & 1;
        asm volatile("cp.async.wait_group 0;" ::: "memory");
        __syncthreads();
        if (kc + 1 < nc) {
            int kglob = (kc + 1) * 16 + sk;
            const void* src = usrc + (size_t)(kglob < LSEQ ? kglob : 0) * BATCH + sj * 8;
            cpasync16(buf ? dstbase0 : dstbase1, src, (kglob < LSEQ) ? 16 : 0);
            asm volatile("cp.async.commit_group;");
        }
        int x0 = REV - m0 - warp * 16 + kc * 16 + t2 - g;
        uint32_t ah0 = pk2(Ksm[0], x0), ah1 = pk2(Ksm[0], x0 - 8), ah2 = pk2(Ksm[0], x0 + 8);
        uint32_t al0 = pk2(Ksm[1], x0), al1 = pk2(Ksm[1], x0 - 8), al2 = pk2(Ksm[1], x0 + 8);
        uint32_t baseh = smaddr(&Usm[buf][0][0]) + rowoff;
        uint32_t basel = smaddr(&Usm[buf][1][0]) + rowoff;
#pragma unroll
        for (int ng = 0; ng < 4; ng++) {
            uint32_t unit = (uint32_t)(((ng * 2 + bg) ^ r) << 4);
            uint32_t r0, r1, r2, r3, s0, s1, s2, s3;
            ldsm4t(r0, r1, r2, r3, baseh + unit);
            ldsm4t(s0, s1, s2, s3, basel + unit);
            mma16816(acc[2 * ng],     ah0, ah1, ah2, ah0, r0, r1);
            mma16816(acc[2 * ng],     ah0, ah1, ah2, ah0, s0, s1);
            mma16816(acc[2 * ng],     al0, al1, al2, al0, r0, r1);
            mma16816(acc[2 * ng + 1], ah0, ah1, ah2, ah0, r2, r3);
            mma16816(acc[2 * ng + 1], ah0, ah1, ah2, ah0, s2, s3);
            mma16816(acc[2 * ng + 1], al0, al1, al2, al0, r2, r3);
        }
    }

    // epilogue: z = (1+D)*u + conv, into g_y (H,L,B)
    float D1 = 1.0f + Dvec[layer * HDIM + h];
    float* Z = g_y + (size_t)h * (LSEQ * BATCH);
    int R0 = m0 + warp * 16 + g;
    int R1 = R0 + 8;
#pragma unroll
    for (int u = 0; u < 8; u++) {
        int b = u * 8 + t2;
        if (R0 < LSEQ) {
            size_t o = (size_t)R0 * BATCH + b;
            Z[o]     = fmaf(D1, U[o], acc[u][0]);
            Z[o + 1] = fmaf(D1, U[o + 1], acc[u][1]);
        }
        if (R1 < LSEQ) {
            size_t o = (size_t)R1 * BATCH + b;
            Z[o]     = fmaf(D1, U[o], acc[u][2]);
            Z[o + 1] = fmaf(D1, U[o + 1], acc[u][3]);
        }
    }
}

// -------- layernorm over H, (H,L,B) layout, optional bf16-split output --------
__global__ void __launch_bounds__(512) ln_kernel(const float* __restrict__ gamma,
                                                 const float* __restrict__ beta,
                                                 int addY, int writeBF) {
    int l = blockIdx.x;
    int b0 = blockIdx.y * 16;
    int lx = threadIdx.x & 15;
    int hy = threadIdx.x >> 4;
    __shared__ float z[HDIM][16];
    __shared__ float s1s[32][16], s2s[32][16];
    __shared__ float smean[16], srstd[16];
    const float* src = addY ? g_y : g_h;
    float s1 = 0.0f, s2 = 0.0f;
    for (int h = hy; h < HDIM; h += 32) {
        size_t off = ((size_t)h * LSEQ + l) * BATCH + b0 + lx;
        float v = src[off];
        z[h][lx] = v;
        s1 += v; s2 += v * v;
    }
    s1s[hy][lx] = s1; s2s[hy][lx] = s2;
    __syncthreads();
    for (int st = 16; st >= 1; st >>= 1) {
        if (hy < st) { s1s[hy][lx] += s1s[hy + st][lx]; s2s[hy][lx] += s2s[hy + st][lx]; }
        __syncthreads();
    }
    if (hy == 0) {
        float mean = s1s[0][lx] * (1.0f / HDIM);
        float var = s2s[0][lx] * (1.0f / HDIM) - mean * mean;
        smean[lx] = mean;
        srstd[lx] = rsqrtf(var + 1e-5f);
    }
    __syncthreads();
    float mean = smean[lx], rstd = srstd[lx];
    for (int h = hy; h < HDIM; h += 32) {
        size_t off = ((size_t)h * LSEQ + l) * BATCH + b0 + lx;
        float v = (z[h][lx] - mean) * rstd * gamma[h] + beta[h];
        g_h[off] = v;
        if (writeBF) {
            __nv_bfloat16 hi = __float2bfloat16(v);
            g_ubhi[off] = hi;
            g_ublo[off] = __float2bfloat16(v - __bfloat162float(hi));
        }
    }
}

// -------- mean-pool over L --------
__global__ void __launch_bounds__(256) pool_kernel() {
    int h = blockIdx.x;
    int b = threadIdx.x & 63, part = threadIdx.x >> 6;
    float s = 0.0f;
    for (int l = part; l < LSEQ; l += 4)
        s += g_h[((size_t)h * LSEQ + l) * BATCH + b];
    __shared__ float red[4][64];
    red[part][b] = s;
    __syncthreads();
    if (part == 0)
        g_pool[h * BATCH + b] = (red[0][b] + red[1][b] + red[2][b] + red[3][b]) * (1.0f / LSEQ);
}

// -------- decode to 10 classes --------
__global__ void __launch_bounds__(256) decode_kernel(const float* __restrict__ dec_w,
                                                     const float* __restrict__ dec_b,
                                                     float* __restrict__ out) {
    int b = blockIdx.x;
    int t = threadIdx.x;
    float acc[10];
#pragma unroll
    for (int k = 0; k < 10; k++) acc[k] = 0.0f;
    for (int h = t; h < HDIM; h += 256) {
        float p = g_pool[h * BATCH + b];
#pragma unroll
        for (int k = 0; k < 10; k++) acc[k] = fmaf(p, dec_w[h * 10 + k], acc[k]);
    }
    __shared__ float red[256];
    for (int k = 0; k < 10; k++) {
        red[t] = acc[k];
        __syncthreads();
        for (int st = 128; st >= 1; st >>= 1) {
            if (t < st) red[t] += red[t + st];
            __syncthreads();
        }
        if (t == 0) out[b * 10 + k] = red[0] + dec_b[k];
        __syncthreads();
    }
}

extern "C" void kernel_launch(void* const* d_in, const int* in_sizes, int n_in,
                              void* d_out, int out_size) {
    const float* x          = (const float*)d_in[0];
    const float* enc_w      = (const float*)d_in[1];
    const float* enc_b      = (const float*)d_in[2];
    const float* log_dt     = (const float*)d_in[3];
    const float* log_A_real = (const float*)d_in[4];
    const float* A_imag     = (const float*)d_in[5];
    const float* C_re       = (const float*)d_in[6];
    const float* C_im       = (const float*)d_in[7];
    const float* Dvec       = (const float*)d_in[8];
    const float* ln_g       = (const float*)d_in[9];
    const float* ln_b       = (const float*)d_in[10];
    const float* fn_g       = (const float*)d_in[11];
    const float* fn_b       = (const float*)d_in[12];
    const float* dec_w      = (const float*)d_in[13];
    const float* dec_b      = (const float*)d_in[14];
    float* out = (float*)d_out;

    int np = NLAYERS * HDIM * NSTATE;
    precompute_kernel<<<(np + 255) / 256, 256>>>(log_dt, log_A_real, A_imag, C_re, C_im);
    kgen_kernel<<<dim3(HDIM / 16, NLAYERS), 128>>>();
    krr_kernel<<<dim3(HDIM, NLAYERS), 256>>>();
    encoder_kernel<<<LSEQ, 256>>>(x, enc_w, enc_b);

    for (int i = 0; i < NLAYERS; i++) {
        gemm_kernel<<<HDIM * MT, 256>>>(i, Dvec);
        ln_kernel<<<dim3(LSEQ, BATCH / 16), 512>>>(ln_g + i * HDIM, ln_b + i * HDIM, 1,
                                                   i < NLAYERS - 1);
    }
    ln_kernel<<<dim3(LSEQ, BATCH / 16), 512>>>(fn_g, fn_b, 0, 0);
    pool_kernel<<<HDIM, 256>>>();
    decode_kernel<<<BATCH, 256>>>(dec_w, dec_b, out);
}

// round 13
// speedup vs baseline: 1.8494x; 1.1599x over previous
#include <cuda_runtime.h>
#include <cuda_bf16.h>
#include <cstddef>
#include <cstdint>

#define BATCH 64
#define LSEQ 784
#define HDIM 512
#define NSTATE 64
#define NLAYERS 6
#define MT 7             // m-tiles of 128 rows, 7*128 = 896 >= 784
#define REV 895
#define KRRN 1024        // reversed-padded kernel length per h

// -------- scratch (no allocations allowed) --------
__device__ float g_h[(size_t)HDIM * LSEQ * BATCH];   // fp32 activations (only last 2 LNs)
__device__ float g_y[(size_t)HDIM * LSEQ * BATCH];   // z = h + conv(h), (H,L,B)
__device__ __nv_bfloat16 g_ubhi[(size_t)HDIM * LSEQ * BATCH];  // bf16 hi of activations
__device__ __nv_bfloat16 g_ublo[(size_t)HDIM * LSEQ * BATCH];  // bf16 lo of activations
__device__ float g_K[NLAYERS * HDIM * LSEQ];         // conv kernels
__device__ __nv_bfloat16 g_krrhi[(size_t)NLAYERS * HDIM * KRRN];
__device__ __nv_bfloat16 g_krrlo[(size_t)NLAYERS * HDIM * KRRN];
__device__ float g_wr[NLAYERS * HDIM * NSTATE];
__device__ float g_wi[NLAYERS * HDIM * NSTATE];
__device__ float g_cr[NLAYERS * HDIM * NSTATE];
__device__ float g_ci[NLAYERS * HDIM * NSTATE];
__device__ float g_pool[HDIM * BATCH];

// -------- ptx helpers --------
__device__ __forceinline__ uint32_t smaddr(const void* p) {
    return (uint32_t)__cvta_generic_to_shared(p);
}
__device__ __forceinline__ void ldsm4t(uint32_t& r0, uint32_t& r1, uint32_t& r2, uint32_t& r3,
                                       uint32_t addr) {
    asm volatile("ldmatrix.sync.aligned.m8n8.x4.trans.shared.b16 {%0,%1,%2,%3}, [%4];"
                 : "=r"(r0), "=r"(r1), "=r"(r2), "=r"(r3) : "r"(addr));
}
__device__ __forceinline__ void mma16816(float* d, uint32_t a0, uint32_t a1, uint32_t a2,
                                         uint32_t a3, uint32_t b0, uint32_t b1) {
    asm volatile("mma.sync.aligned.m16n8k16.row.col.f32.bf16.bf16.f32 "
                 "{%0,%1,%2,%3}, {%4,%5,%6,%7}, {%8,%9}, {%0,%1,%2,%3};"
                 : "+f"(d[0]), "+f"(d[1]), "+f"(d[2]), "+f"(d[3])
                 : "r"(a0), "r"(a1), "r"(a2), "r"(a3), "r"(b0), "r"(b1));
}
__device__ __forceinline__ uint32_t pk2(const __nv_bfloat16* a, int i) {
    uint32_t lo = *(const uint16_t*)(a + i);
    uint32_t hi = *(const uint16_t*)(a + i + 1);
    return lo | (hi << 16);
}
__device__ __forceinline__ void cpasync16(uint32_t dst, const void* src, int sz) {
    asm volatile("cp.async.cg.shared.global [%0], [%1], 16, %2;"
                 :: "r"(dst), "l"(src), "r"(sz));
}

// -------- precompute discretized SSM params --------
__global__ void precompute_kernel(const float* __restrict__ log_dt,
                                  const float* __restrict__ log_A_real,
                                  const float* __restrict__ A_imag,
                                  const float* __restrict__ C_re,
                                  const float* __restrict__ C_im) {
    int idx = blockIdx.x * blockDim.x + threadIdx.x;
    if (idx >= NLAYERS * HDIM * NSTATE) return;
    int hh = (idx / NSTATE) % HDIM;
    int i = idx / (NSTATE * HDIM);
    float dt = expf(log_dt[i * HDIM + hh]);
    float Ar = -expf(log_A_real[idx]);
    float Ai = A_imag[idx];
    float xr = Ar * dt, xi = Ai * dt;
    float e = expf(xr);
    float wre = e * cosf(xi), wim = e * sinf(xi);
    float em1r = wre - 1.0f, em1i = wim;
    float Cre = C_re[idx], Cim = C_im[idx];
    float tr = Cre * em1r - Cim * em1i;
    float ti = Cre * em1i + Cim * em1r;
    float inv = 1.0f / (Ar * Ar + Ai * Ai);
    g_wr[idx] = wre; g_wi[idx] = wim;
    g_cr[idx] = (tr * Ar + ti * Ai) * inv;
    g_ci[idx] = (ti * Ar - tr * Ai) * inv;
}

// -------- kernel generation: impulse response of the recurrence --------
__global__ void __launch_bounds__(128) kgen_kernel() {
    __shared__ float shy[16][120];
    int tid = threadIdx.x;
    int warp = tid >> 5, lane = tid & 31;
    int g = lane >> 3, lg = lane & 7;
    int pairLocal = warp * 4 + g;
    int h = blockIdx.x * 16 + pairLocal;
    int layer = blockIdx.y;
    int pbase = (layer * HDIM + h) * NSTATE;
    float swr[8], swi[8], scr[8], sci[8], sre[8], sim[8];
#pragma unroll
    for (int j = 0; j < 8; j++) {
        int n = lg + 8 * j;
        swr[j] = g_wr[pbase + n]; swi[j] = g_wi[pbase + n];
        scr[j] = g_cr[pbase + n]; sci[j] = g_ci[pbase + n];
        sre[j] = 0.0f; sim[j] = 0.0f;
    }
    float* krow = g_K + (size_t)(layer * HDIM + h) * LSEQ;
    for (int c0 = 0; c0 < LSEQ; c0 += 112) {
#pragma unroll 4
        for (int l = 0; l < 112; l++) {
            float uv = (c0 + l == 0) ? 1.0f : 0.0f;
            float acc = 0.0f;
#pragma unroll
            for (int j = 0; j < 8; j++) {
                float nr = fmaf(swr[j], sre[j], fmaf(-swi[j], sim[j], uv));
                float ni = fmaf(swr[j], sim[j], swi[j] * sre[j]);
                sre[j] = nr; sim[j] = ni;
                acc = fmaf(scr[j], nr, acc);
                acc = fmaf(-sci[j], ni, acc);
            }
            acc += __shfl_xor_sync(0xffffffffu, acc, 1, 8);
            acc += __shfl_xor_sync(0xffffffffu, acc, 2, 8);
            acc += __shfl_xor_sync(0xffffffffu, acc, 4, 8);
            if (lg == 0) shy[pairLocal][l] = 2.0f * acc;
        }
        __syncwarp();
#pragma unroll
        for (int k = 0; k < 14; k++)
            krow[c0 + lg + 8 * k] = shy[pairLocal][lg + 8 * k];
        __syncwarp();
    }
}

// -------- build reversed zero-padded bf16 hi/lo kernel, residual folded in --------
// KRR[t] = Kpad[REV - t]; K'[0] = K[0] + 1 + D  (so z = Sum K'[d] u[t-d] directly)
__global__ void __launch_bounds__(256) krr_kernel(const float* __restrict__ Dvec) {
    int h = blockIdx.x, layer = blockIdx.y;
    const float* kr = g_K + (size_t)(layer * HDIM + h) * LSEQ;
    __nv_bfloat16* oh = g_krrhi + (size_t)(layer * HDIM + h) * KRRN;
    __nv_bfloat16* ol = g_krrlo + (size_t)(layer * HDIM + h) * KRRN;
    float Dadd = 1.0f + Dvec[layer * HDIM + h];
    for (int t = threadIdx.x; t < KRRN; t += 256) {
        int d = REV - t;
        float v = (d >= 0 && d < LSEQ) ? kr[d] : 0.0f;
        if (d == 0) v += Dadd;
        __nv_bfloat16 hi = __float2bfloat16(v);
        __nv_bfloat16 lo = __float2bfloat16(v - __bfloat162float(hi));
        oh[t] = hi; ol[t] = lo;
    }
}

// -------- encoder: bf16-split activations only (gemm needs nothing else) --------
__global__ void __launch_bounds__(256) encoder_kernel(const float* __restrict__ x,
                                                      const float* __restrict__ enc_w,
                                                      const float* __restrict__ enc_b) {
    int l = blockIdx.x;
    __shared__ float xs[BATCH];
    if (threadIdx.x < BATCH) xs[threadIdx.x] = x[threadIdx.x * LSEQ + l];
    __syncthreads();
    for (int idx = threadIdx.x; idx < HDIM * BATCH; idx += 256) {
        int h = idx >> 6, b = idx & 63;
        size_t off = ((size_t)h * LSEQ + l) * BATCH + b;
        float v = fmaf(xs[b], enc_w[h], enc_b[h]);
        __nv_bfloat16 hi = __float2bfloat16(v);
        g_ubhi[off] = hi;
        g_ublo[off] = __float2bfloat16(v - __bfloat162float(hi));
    }
}

// -------- S4 conv as triangular Toeplitz GEMM, bf16-split, fp32 accum --------
// 256 threads / 8 warps. Block: (h, 128-row m-tile). k-chunks of 32.
// B staged by cp.async as Usm[k][b] rows of 128B, swizzle unit ^= (k&7).
__global__ void __launch_bounds__(256) gemm_kernel(int layer) {
    __shared__ __align__(16) __nv_bfloat16 Ksm[2][KRRN];          // hi, lo (4KB)
    __shared__ __align__(16) uint8_t Usm[2][2][32 * 128];         // [buf][plane] (16KB)
    int tid = threadIdx.x;
    int id = blockIdx.x;
    int mt = id % MT;
    int h = id / MT;
    int m0 = mt * 128;
    int warp = tid >> 5, lane = tid & 31;
    int g = lane >> 2, t2 = (lane & 3) * 2;

    {   // load kernel slice (hi+lo) vectorized
        const uint4* kh4 = (const uint4*)(g_krrhi + (size_t)(layer * HDIM + h) * KRRN);
        const uint4* kl4 = (const uint4*)(g_krrlo + (size_t)(layer * HDIM + h) * KRRN);
        int p = tid >> 7, j = tid & 127;          // 128 uint4 per plane
        ((uint4*)Ksm[p])[j] = p ? kl4[j] : kh4[j];
    }

    // staging: 2 planes x 128 threads; each thread copies rows sk and sk+16 (16B each)
    const __nv_bfloat16* usrc0 = g_ubhi + (size_t)h * (LSEQ * BATCH);
    const __nv_bfloat16* usrc1 = g_ublo + (size_t)h * (LSEQ * BATCH);
    int sp = tid >> 7;
    const __nv_bfloat16* usrc = sp ? usrc1 : usrc0;
    int si = tid & 127;
    int sk = si >> 3, sj = si & 7;               // sk 0..15, second row = sk+16
    uint32_t doffA = (uint32_t)(sk * 128 + ((sj ^ (sk & 7)) << 4));
    uint32_t doffB = (uint32_t)((sk + 16) * 128 + ((sj ^ ((sk + 16) & 7)) << 4));
    uint32_t base0 = smaddr(&Usm[0][sp][0]);
    uint32_t base1 = smaddr(&Usm[1][sp][0]);

    int nc = mt * 4 + 4;   // 32-wide chunks cover k < m0+128

    // prologue: issue chunk 0 (rows < 784 always)
    cpasync16(base0 + doffA, usrc + (size_t)sk * BATCH + sj * 8, 16);
    cpasync16(base0 + doffB, usrc + (size_t)(sk + 16) * BATCH + sj * 8, 16);
    asm volatile("cp.async.commit_group;");

    float acc[8][4];
#pragma unroll
    for (int u = 0; u < 8; u++)
#pragma unroll
        for (int c = 0; c < 4; c++) acc[u][c] = 0.0f;

    // ldmatrix.trans lane mapping
    int r = lane & 7, mm = lane >> 3;
    int khh = mm & 1, bg = mm >> 1;
    uint32_t rowoff = (uint32_t)((khh * 8 + r) * 128);

    for (int kc = 0; kc < nc; kc++) {
        int buf = kc & 1;
        asm volatile("cp.async.wait_group 0;" ::: "memory");
        __syncthreads();
        if (kc + 1 < nc) {
            int kbase = (kc + 1) * 32;
            int kA = kbase + sk, kB = kbase + sk + 16;
            uint32_t nb = buf ? base0 : base1;
            cpasync16(nb + doffA, usrc + (size_t)(kA < LSEQ ? kA : 0) * BATCH + sj * 8,
                      (kA < LSEQ) ? 16 : 0);
            cpasync16(nb + doffB, usrc + (size_t)(kB < LSEQ ? kB : 0) * BATCH + sj * 8,
                      (kB < LSEQ) ? 16 : 0);
            asm volatile("cp.async.commit_group;");
        }
        uint32_t bh = smaddr(&Usm[buf][0][0]) + rowoff;
        uint32_t bl = smaddr(&Usm[buf][1][0]) + rowoff;
#pragma unroll
        for (int kk = 0; kk < 32; kk += 16) {
            int x0 = REV - m0 - warp * 16 + kc * 32 + kk + t2 - g;
            uint32_t ah0 = pk2(Ksm[0], x0), ah1 = pk2(Ksm[0], x0 - 8), ah2 = pk2(Ksm[0], x0 + 8);
            uint32_t al0 = pk2(Ksm[1], x0), al1 = pk2(Ksm[1], x0 - 8), al2 = pk2(Ksm[1], x0 + 8);
            uint32_t kof = (uint32_t)(kk * 128);
#pragma unroll
            for (int ng = 0; ng < 4; ng++) {
                uint32_t unit = (uint32_t)(((ng * 2 + bg) ^ r) << 4);
                uint32_t r0, r1, r2, r3, s0, s1, s2, s3;
                ldsm4t(r0, r1, r2, r3, bh + kof + unit);
                ldsm4t(s0, s1, s2, s3, bl + kof + unit);
                mma16816(acc[2 * ng],     ah0, ah1, ah2, ah0, r0, r1);
                mma16816(acc[2 * ng],     ah0, ah1, ah2, ah0, s0, s1);
                mma16816(acc[2 * ng],     al0, al1, al2, al0, r0, r1);
                mma16816(acc[2 * ng + 1], ah0, ah1, ah2, ah0, r2, r3);
                mma16816(acc[2 * ng + 1], ah0, ah1, ah2, ah0, s2, s3);
                mma16816(acc[2 * ng + 1], al0, al1, al2, al0, r2, r3);
            }
        }
    }

    // epilogue: z = acc (residual + D folded into K'), into g_y (H,L,B)
    float* Z = g_y + (size_t)h * (LSEQ * BATCH);
    int R0 = m0 + warp * 16 + g;
    int R1 = R0 + 8;
#pragma unroll
    for (int u = 0; u < 8; u++) {
        int b = u * 8 + t2;
        if (R0 < LSEQ) {
            size_t o = (size_t)R0 * BATCH + b;
            Z[o] = acc[u][0]; Z[o + 1] = acc[u][1];
        }
        if (R1 < LSEQ) {
            size_t o = (size_t)R1 * BATCH + b;
            Z[o] = acc[u][2]; Z[o + 1] = acc[u][3];
        }
    }
}

// -------- layernorm over H, (H,L,B) layout --------
__global__ void __launch_bounds__(512) ln_kernel(const float* __restrict__ gamma,
                                                 const float* __restrict__ beta,
                                                 int addY, int writeFP, int writeBF) {
    int l = blockIdx.x;
    int b0 = blockIdx.y * 16;
    int lx = threadIdx.x & 15;
    int hy = threadIdx.x >> 4;
    __shared__ float z[HDIM][16];
    __shared__ float s1s[32][16], s2s[32][16];
    __shared__ float smean[16], srstd[16];
    const float* src = addY ? g_y : g_h;
    float s1 = 0.0f, s2 = 0.0f;
    for (int h = hy; h < HDIM; h += 32) {
        size_t off = ((size_t)h * LSEQ + l) * BATCH + b0 + lx;
        float v = src[off];
        z[h][lx] = v;
        s1 += v; s2 += v * v;
    }
    s1s[hy][lx] = s1; s2s[hy][lx] = s2;
    __syncthreads();
    for (int st = 16; st >= 1; st >>= 1) {
        if (hy < st) { s1s[hy][lx] += s1s[hy + st][lx]; s2s[hy][lx] += s2s[hy + st][lx]; }
        __syncthreads();
    }
    if (hy == 0) {
        float mean = s1s[0][lx] * (1.0f / HDIM);
        float var = s2s[0][lx] * (1.0f / HDIM) - mean * mean;
        smean[lx] = mean;
        srstd[lx] = rsqrtf(var + 1e-5f);
    }
    __syncthreads();
    float mean = smean[lx], rstd = srstd[lx];
    for (int h = hy; h < HDIM; h += 32) {
        size_t off = ((size_t)h * LSEQ + l) * BATCH + b0 + lx;
        float v = (z[h][lx] - mean) * rstd * gamma[h] + beta[h];
        if (writeFP) g_h[off] = v;
        if (writeBF) {
            __nv_bfloat16 hi = __float2bfloat16(v);
            g_ubhi[off] = hi;
            g_ublo[off] = __float2bfloat16(v - __bfloat162float(hi));
        }
    }
}

// -------- mean-pool over L --------
__global__ void __launch_bounds__(256) pool_kernel() {
    int h = blockIdx.x;
    int b = threadIdx.x & 63, part = threadIdx.x >> 6;
    float s = 0.0f;
    for (int l = part; l < LSEQ; l += 4)
        s += g_h[((size_t)h * LSEQ + l) * BATCH + b];
    __shared__ float red[4][64];
    red[part][b] = s;
    __syncthreads();
    if (part == 0)
        g_pool[h * BATCH + b] = (red[0][b] + red[1][b] + red[2][b] + red[3][b]) * (1.0f / LSEQ);
}

// -------- decode to 10 classes --------
__global__ void __launch_bounds__(256) decode_kernel(const float* __restrict__ dec_w,
                                                     const float* __restrict__ dec_b,
                                                     float* __restrict__ out) {
    int b = blockIdx.x;
    int t = threadIdx.x;
    float acc[10];
#pragma unroll
    for (int k = 0; k < 10; k++) acc[k] = 0.0f;
    for (int h = t; h < HDIM; h += 256) {
        float p = g_pool[h * BATCH + b];
#pragma unroll
        for (int k = 0; k < 10; k++) acc[k] = fmaf(p, dec_w[h * 10 + k], acc[k]);
    }
    __shared__ float red[256];
    for (int k = 0; k < 10; k++) {
        red[t] = acc[k];
        __syncthreads();
        for (int st = 128; st >= 1; st >>= 1) {
            if (t < st) red[t] += red[t + st];
            __syncthreads();
        }
        if (t == 0) out[b * 10 + k] = red[0] + dec_b[k];
        __syncthreads();
    }
}

extern "C" void kernel_launch(void* const* d_in, const int* in_sizes, int n_in,
                              void* d_out, int out_size) {
    const float* x          = (const float*)d_in[0];
    const float* enc_w      = (const float*)d_in[1];
    const float* enc_b      = (const float*)d_in[2];
    const float* log_dt     = (const float*)d_in[3];
    const float* log_A_real = (const float*)d_in[4];
    const float* A_imag     = (const float*)d_in[5];
    const float* C_re       = (const float*)d_in[6];
    const float* C_im       = (const float*)d_in[7];
    const float* Dvec       = (const float*)d_in[8];
    const float* ln_g       = (const float*)d_in[9];
    const float* ln_b       = (const float*)d_in[10];
    const float* fn_g       = (const float*)d_in[11];
    const float* fn_b       = (const float*)d_in[12];
    const float* dec_w      = (const float*)d_in[13];
    const float* dec_b      = (const float*)d_in[14];
    float* out = (float*)d_out;

    int np = NLAYERS * HDIM * NSTATE;
    precompute_kernel<<<(np + 255) / 256, 256>>>(log_dt, log_A_real, A_imag, C_re, C_im);
    kgen_kernel<<<dim3(HDIM / 16, NLAYERS), 128>>>();
    krr_kernel<<<dim3(HDIM, NLAYERS), 256>>>(Dvec);
    encoder_kernel<<<LSEQ, 256>>>(x, enc_w, enc_b);

    for (int i = 0; i < NLAYERS; i++) {
        gemm_kernel<<<HDIM * MT, 256>>>(i);
        int last = (i == NLAYERS - 1);
        ln_kernel<<<dim3(LSEQ, BATCH / 16), 512>>>(ln_g + i * HDIM, ln_b + i * HDIM,
                                                   1, last, !last);
    }
    ln_kernel<<<dim3(LSEQ, BATCH / 16), 512>>>(fn_g, fn_b, 0, 1, 0);
    pool_kernel<<<HDIM, 256>>>();
    decode_kernel<<<BATCH, 256>>>(dec_w, dec_b, out);
}

// round 14
// speedup vs baseline: 2.1596x; 1.1677x over previous
#include <cuda_runtime.h>
#include <cuda_bf16.h>
#include <cstddef>
#include <cstdint>

#define BATCH 64
#define LSEQ 784
#define HDIM 512
#define NSTATE 64
#define NLAYERS 6
#define MT 7             // m-tiles of 128 rows, 7*128 = 896 >= 784
#define REV 895
#define KRRN 1024        // reversed-padded kernel length per h

// -------- scratch (no allocations allowed) --------
__device__ float g_h[(size_t)HDIM * LSEQ * BATCH];   // fp32 activations (only last 2 LNs)
__device__ float g_y[(size_t)HDIM * LSEQ * BATCH];   // z = h + conv(h), (H,L,B)
__device__ __nv_bfloat16 g_ubhi[(size_t)HDIM * LSEQ * BATCH];  // bf16 hi of activations
__device__ __nv_bfloat16 g_ublo[(size_t)HDIM * LSEQ * BATCH];  // bf16 lo of activations
__device__ float g_K[NLAYERS * HDIM * LSEQ];         // conv kernels
__device__ __nv_bfloat16 g_krrhi[(size_t)NLAYERS * HDIM * KRRN];
__device__ __nv_bfloat16 g_krrlo[(size_t)NLAYERS * HDIM * KRRN];
__device__ float g_wr[NLAYERS * HDIM * NSTATE];
__device__ float g_wi[NLAYERS * HDIM * NSTATE];
__device__ float g_cr[NLAYERS * HDIM * NSTATE];
__device__ float g_ci[NLAYERS * HDIM * NSTATE];
__device__ float g_pool[HDIM * BATCH];

// -------- ptx helpers --------
__device__ __forceinline__ uint32_t smaddr(const void* p) {
    return (uint32_t)__cvta_generic_to_shared(p);
}
__device__ __forceinline__ void ldsm4t(uint32_t& r0, uint32_t& r1, uint32_t& r2, uint32_t& r3,
                                       uint32_t addr) {
    asm volatile("ldmatrix.sync.aligned.m8n8.x4.trans.shared.b16 {%0,%1,%2,%3}, [%4];"
                 : "=r"(r0), "=r"(r1), "=r"(r2), "=r"(r3) : "r"(addr));
}
__device__ __forceinline__ void mma16816(float* d, uint32_t a0, uint32_t a1, uint32_t a2,
                                         uint32_t a3, uint32_t b0, uint32_t b1) {
    asm volatile("mma.sync.aligned.m16n8k16.row.col.f32.bf16.bf16.f32 "
                 "{%0,%1,%2,%3}, {%4,%5,%6,%7}, {%8,%9}, {%0,%1,%2,%3};"
                 : "+f"(d[0]), "+f"(d[1]), "+f"(d[2]), "+f"(d[3])
                 : "r"(a0), "r"(a1), "r"(a2), "r"(a3), "r"(b0), "r"(b1));
}
__device__ __forceinline__ uint32_t pk2(const __nv_bfloat16* a, int i) {
    uint32_t lo = *(const uint16_t*)(a + i);
    uint32_t hi = *(const uint16_t*)(a + i + 1);
    return lo | (hi << 16);
}
__device__ __forceinline__ void cpasync16(uint32_t dst, const void* src, int sz) {
    asm volatile("cp.async.cg.shared.global [%0], [%1], 16, %2;"
                 :: "r"(dst), "l"(src), "r"(sz));
}

// -------- precompute discretized SSM params --------
__global__ void precompute_kernel(const float* __restrict__ log_dt,
                                  const float* __restrict__ log_A_real,
                                  const float* __restrict__ A_imag,
                                  const float* __restrict__ C_re,
                                  const float* __restrict__ C_im) {
    int idx = blockIdx.x * blockDim.x + threadIdx.x;
    if (idx >= NLAYERS * HDIM * NSTATE) return;
    int hh = (idx / NSTATE) % HDIM;
    int i = idx / (NSTATE * HDIM);
    float dt = expf(log_dt[i * HDIM + hh]);
    float Ar = -expf(log_A_real[idx]);
    float Ai = A_imag[idx];
    float xr = Ar * dt, xi = Ai * dt;
    float e = expf(xr);
    float wre = e * cosf(xi), wim = e * sinf(xi);
    float em1r = wre - 1.0f, em1i = wim;
    float Cre = C_re[idx], Cim = C_im[idx];
    float tr = Cre * em1r - Cim * em1i;
    float ti = Cre * em1i + Cim * em1r;
    float inv = 1.0f / (Ar * Ar + Ai * Ai);
    g_wr[idx] = wre; g_wi[idx] = wim;
    g_cr[idx] = (tr * Ar + ti * Ai) * inv;
    g_ci[idx] = (ti * Ar - tr * Ai) * inv;
}

// -------- kernel generation: impulse response of the recurrence --------
__global__ void __launch_bounds__(128) kgen_kernel() {
    __shared__ float shy[16][120];
    int tid = threadIdx.x;
    int warp = tid >> 5, lane = tid & 31;
    int g = lane >> 3, lg = lane & 7;
    int pairLocal = warp * 4 + g;
    int h = blockIdx.x * 16 + pairLocal;
    int layer = blockIdx.y;
    int pbase = (layer * HDIM + h) * NSTATE;
    float swr[8], swi[8], scr[8], sci[8], sre[8], sim[8];
#pragma unroll
    for (int j = 0; j < 8; j++) {
        int n = lg + 8 * j;
        swr[j] = g_wr[pbase + n]; swi[j] = g_wi[pbase + n];
        scr[j] = g_cr[pbase + n]; sci[j] = g_ci[pbase + n];
        sre[j] = 0.0f; sim[j] = 0.0f;
    }
    float* krow = g_K + (size_t)(layer * HDIM + h) * LSEQ;
    for (int c0 = 0; c0 < LSEQ; c0 += 112) {
#pragma unroll 4
        for (int l = 0; l < 112; l++) {
            float uv = (c0 + l == 0) ? 1.0f : 0.0f;
            float acc = 0.0f;
#pragma unroll
            for (int j = 0; j < 8; j++) {
                float nr = fmaf(swr[j], sre[j], fmaf(-swi[j], sim[j], uv));
                float ni = fmaf(swr[j], sim[j], swi[j] * sre[j]);
                sre[j] = nr; sim[j] = ni;
                acc = fmaf(scr[j], nr, acc);
                acc = fmaf(-sci[j], ni, acc);
            }
            acc += __shfl_xor_sync(0xffffffffu, acc, 1, 8);
            acc += __shfl_xor_sync(0xffffffffu, acc, 2, 8);
            acc += __shfl_xor_sync(0xffffffffu, acc, 4, 8);
            if (lg == 0) shy[pairLocal][l] = 2.0f * acc;
        }
        __syncwarp();
#pragma unroll
        for (int k = 0; k < 14; k++)
            krow[c0 + lg + 8 * k] = shy[pairLocal][lg + 8 * k];
        __syncwarp();
    }
}

// -------- build reversed zero-padded bf16 hi/lo kernel, residual folded in --------
// KRR[t] = Kpad[REV - t]; K'[0] = K[0] + 1 + D  (so z = Sum K'[d] u[t-d] directly)
__global__ void __launch_bounds__(256) krr_kernel(const float* __restrict__ Dvec) {
    int h = blockIdx.x, layer = blockIdx.y;
    const float* kr = g_K + (size_t)(layer * HDIM + h) * LSEQ;
    __nv_bfloat16* oh = g_krrhi + (size_t)(layer * HDIM + h) * KRRN;
    __nv_bfloat16* ol = g_krrlo + (size_t)(layer * HDIM + h) * KRRN;
    float Dadd = 1.0f + Dvec[layer * HDIM + h];
    for (int t = threadIdx.x; t < KRRN; t += 256) {
        int d = REV - t;
        float v = (d >= 0 && d < LSEQ) ? kr[d] : 0.0f;
        if (d == 0) v += Dadd;
        __nv_bfloat16 hi = __float2bfloat16(v);
        __nv_bfloat16 lo = __float2bfloat16(v - __bfloat162float(hi));
        oh[t] = hi; ol[t] = lo;
    }
}

// -------- encoder: bf16-split activations only --------
__global__ void __launch_bounds__(256) encoder_kernel(const float* __restrict__ x,
                                                      const float* __restrict__ enc_w,
                                                      const float* __restrict__ enc_b) {
    int l = blockIdx.x;
    __shared__ float xs[BATCH];
    if (threadIdx.x < BATCH) xs[threadIdx.x] = x[threadIdx.x * LSEQ + l];
    __syncthreads();
    for (int idx = threadIdx.x; idx < HDIM * BATCH; idx += 256) {
        int h = idx >> 6, b = idx & 63;
        size_t off = ((size_t)h * LSEQ + l) * BATCH + b;
        float v = fmaf(xs[b], enc_w[h], enc_b[h]);
        __nv_bfloat16 hi = __float2bfloat16(v);
        g_ubhi[off] = hi;
        g_ublo[off] = __float2bfloat16(v - __bfloat162float(hi));
    }
}

// -------- S4 conv as triangular Toeplitz GEMM, bf16-split, fp32 accum --------
// 256 threads / 8 warps. Block: (h, 128-row m-tile). k-chunks of 32.
// 3-stage cp.async pipeline (wait_group 1), swizzle unit ^= (k&7).
__global__ void __launch_bounds__(256) gemm_kernel(int layer) {
    __shared__ __align__(16) __nv_bfloat16 Ksm[2][KRRN];          // hi, lo (4KB)
    __shared__ __align__(16) uint8_t Usm[3][2][32 * 128];         // [buf][plane] (24KB)
    int tid = threadIdx.x;
    int id = blockIdx.x;
    int mt = id % MT;
    int h = id / MT;
    int m0 = mt * 128;
    int warp = tid >> 5, lane = tid & 31;
    int g = lane >> 2, t2 = (lane & 3) * 2;

    {   // load kernel slice (hi+lo) vectorized
        const uint4* kh4 = (const uint4*)(g_krrhi + (size_t)(layer * HDIM + h) * KRRN);
        const uint4* kl4 = (const uint4*)(g_krrlo + (size_t)(layer * HDIM + h) * KRRN);
        int p = tid >> 7, j = tid & 127;          // 128 uint4 per plane
        ((uint4*)Ksm[p])[j] = p ? kl4[j] : kh4[j];
    }

    // staging: 2 planes x 128 threads; each thread copies rows sk and sk+16 (16B each)
    const __nv_bfloat16* usrc0 = g_ubhi + (size_t)h * (LSEQ * BATCH);
    const __nv_bfloat16* usrc1 = g_ublo + (size_t)h * (LSEQ * BATCH);
    int sp = tid >> 7;
    const __nv_bfloat16* usrc = sp ? usrc1 : usrc0;
    int si = tid & 127;
    int sk = si >> 3, sj = si & 7;               // sk 0..15, second row = sk+16
    uint32_t doffA = (uint32_t)(sk * 128 + ((sj ^ (sk & 7)) << 4));
    uint32_t doffB = (uint32_t)((sk + 16) * 128 + ((sj ^ ((sk + 16) & 7)) << 4));
    uint32_t sbase[3] = { smaddr(&Usm[0][sp][0]), smaddr(&Usm[1][sp][0]),
                          smaddr(&Usm[2][sp][0]) };

    int nc = mt * 4 + 4;   // 32-wide chunks cover k < m0+128

    // prologue: issue chunks 0 and 1 (chunk 0 rows always < 784)
    cpasync16(sbase[0] + doffA, usrc + (size_t)sk * BATCH + sj * 8, 16);
    cpasync16(sbase[0] + doffB, usrc + (size_t)(sk + 16) * BATCH + sj * 8, 16);
    asm volatile("cp.async.commit_group;");
    {
        int kA = 32 + sk, kB = 32 + sk + 16;
        cpasync16(sbase[1] + doffA, usrc + (size_t)(kA < LSEQ ? kA : 0) * BATCH + sj * 8,
                  (kA < LSEQ) ? 16 : 0);
        cpasync16(sbase[1] + doffB, usrc + (size_t)(kB < LSEQ ? kB : 0) * BATCH + sj * 8,
                  (kB < LSEQ) ? 16 : 0);
        asm volatile("cp.async.commit_group;");
    }

    float acc[8][4];
#pragma unroll
    for (int u = 0; u < 8; u++)
#pragma unroll
        for (int c = 0; c < 4; c++) acc[u][c] = 0.0f;

    // ldmatrix.trans lane mapping
    int r = lane & 7, mm = lane >> 3;
    int khh = mm & 1, bg = mm >> 1;
    uint32_t rowoff = (uint32_t)((khh * 8 + r) * 128);

    int buf = 0;
    for (int kc = 0; kc < nc; kc++) {
        asm volatile("cp.async.wait_group 1;" ::: "memory");
        __syncthreads();
        // issue chunk kc+2 into the buffer freed by chunk kc-1
        {
            int kbase = (kc + 2) * 32;
            if (kc + 2 < nc) {
                int nb = buf + 2; if (nb >= 3) nb -= 3;
                int kA = kbase + sk, kB = kbase + sk + 16;
                cpasync16(sbase[nb] + doffA,
                          usrc + (size_t)(kA < LSEQ ? kA : 0) * BATCH + sj * 8,
                          (kA < LSEQ) ? 16 : 0);
                cpasync16(sbase[nb] + doffB,
                          usrc + (size_t)(kB < LSEQ ? kB : 0) * BATCH + sj * 8,
                          (kB < LSEQ) ? 16 : 0);
            }
            asm volatile("cp.async.commit_group;");   // empty group ok at tail
        }
        uint32_t bh = smaddr(&Usm[buf][0][0]) + rowoff;
        uint32_t bl = smaddr(&Usm[buf][1][0]) + rowoff;
#pragma unroll
        for (int kk = 0; kk < 32; kk += 16) {
            int x0 = REV - m0 - warp * 16 + kc * 32 + kk + t2 - g;
            uint32_t ah0 = pk2(Ksm[0], x0), ah1 = pk2(Ksm[0], x0 - 8), ah2 = pk2(Ksm[0], x0 + 8);
            uint32_t al0 = pk2(Ksm[1], x0), al1 = pk2(Ksm[1], x0 - 8), al2 = pk2(Ksm[1], x0 + 8);
            uint32_t kof = (uint32_t)(kk * 128);
#pragma unroll
            for (int ng = 0; ng < 4; ng++) {
                uint32_t unit = (uint32_t)(((ng * 2 + bg) ^ r) << 4);
                uint32_t r0, r1, r2, r3, s0, s1, s2, s3;
                ldsm4t(r0, r1, r2, r3, bh + kof + unit);
                ldsm4t(s0, s1, s2, s3, bl + kof + unit);
                mma16816(acc[2 * ng],     ah0, ah1, ah2, ah0, r0, r1);
                mma16816(acc[2 * ng],     ah0, ah1, ah2, ah0, s0, s1);
                mma16816(acc[2 * ng],     al0, al1, al2, al0, r0, r1);
                mma16816(acc[2 * ng + 1], ah0, ah1, ah2, ah0, r2, r3);
                mma16816(acc[2 * ng + 1], ah0, ah1, ah2, ah0, s2, s3);
                mma16816(acc[2 * ng + 1], al0, al1, al2, al0, r2, r3);
            }
        }
        buf++; if (buf == 3) buf = 0;
    }

    // epilogue: z = acc (residual + D folded into K'), into g_y (H,L,B)
    float* Z = g_y + (size_t)h * (LSEQ * BATCH);
    int R0 = m0 + warp * 16 + g;
    int R1 = R0 + 8;
#pragma unroll
    for (int u = 0; u < 8; u++) {
        int b = u * 8 + t2;
        if (R0 < LSEQ) {
            size_t o = (size_t)R0 * BATCH + b;
            Z[o] = acc[u][0]; Z[o + 1] = acc[u][1];
        }
        if (R1 < LSEQ) {
            size_t o = (size_t)R1 * BATCH + b;
            Z[o] = acc[u][2]; Z[o + 1] = acc[u][3];
        }
    }
}

// -------- layernorm over H, (H,L,B) layout, coalesced two-pass --------
// block = one l. thread = (b = t&63, hp = t>>6). Every warp reads 32 consecutive
// fp32 per h-step (128B transactions). Second pass re-reads via L2 (128KB WS).
__global__ void __launch_bounds__(512) ln_kernel(const float* __restrict__ gamma,
                                                 const float* __restrict__ beta,
                                                 int addY, int writeFP, int writeBF) {
    int l = blockIdx.x;
    int t = threadIdx.x;
    int b = t & 63, hp = t >> 6;   // hp 0..7
    const float* src = (addY ? g_y : g_h) + (size_t)l * BATCH;
    float s1 = 0.0f, s2 = 0.0f;
    for (int h = hp; h < HDIM; h += 8) {
        float v = __ldg(src + (size_t)h * (LSEQ * BATCH) + b);
        s1 += v; s2 += v * v;
    }
    __shared__ float r1[8][64], r2[8][64];
    __shared__ float smean[64], srstd[64];
    r1[hp][b] = s1; r2[hp][b] = s2;
    __syncthreads();
    if (t < 64) {
        float a1 = 0.0f, a2 = 0.0f;
#pragma unroll
        for (int i = 0; i < 8; i++) { a1 += r1[i][t]; a2 += r2[i][t]; }
        float mean = a1 * (1.0f / HDIM);
        float var = a2 * (1.0f / HDIM) - mean * mean;
        smean[t] = mean;
        srstd[t] = rsqrtf(var + 1e-5f);
    }
    __syncthreads();
    float mean = smean[b], rstd = srstd[b];
    size_t lb = (size_t)l * BATCH;
    for (int h = hp; h < HDIM; h += 8) {
        size_t off = (size_t)h * (LSEQ * BATCH) + lb + b;
        float v = (__ldg(src + (size_t)h * (LSEQ * BATCH) + b) - mean) * rstd * gamma[h]
                  + beta[h];
        if (writeFP) g_h[off] = v;
        if (writeBF) {
            __nv_bfloat16 hi = __float2bfloat16(v);
            g_ubhi[off] = hi;
            g_ublo[off] = __float2bfloat16(v - __bfloat162float(hi));
        }
    }
}

// -------- mean-pool over L --------
__global__ void __launch_bounds__(256) pool_kernel() {
    int h = blockIdx.x;
    int b = threadIdx.x & 63, part = threadIdx.x >> 6;
    float s = 0.0f;
    for (int l = part; l < LSEQ; l += 4)
        s += g_h[((size_t)h * LSEQ + l) * BATCH + b];
    __shared__ float red[4][64];
    red[part][b] = s;
    __syncthreads();
    if (part == 0)
        g_pool[h * BATCH + b] = (red[0][b] + red[1][b] + red[2][b] + red[3][b]) * (1.0f / LSEQ);
}

// -------- decode to 10 classes --------
__global__ void __launch_bounds__(256) decode_kernel(const float* __restrict__ dec_w,
                                                     const float* __restrict__ dec_b,
                                                     float* __restrict__ out) {
    int b = blockIdx.x;
    int t = threadIdx.x;
    float acc[10];
#pragma unroll
    for (int k = 0; k < 10; k++) acc[k] = 0.0f;
    for (int h = t; h < HDIM; h += 256) {
        float p = g_pool[h * BATCH + b];
#pragma unroll
        for (int k = 0; k < 10; k++) acc[k] = fmaf(p, dec_w[h * 10 + k], acc[k]);
    }
    __shared__ float red[256];
    for (int k = 0; k < 10; k++) {
        red[t] = acc[k];
        __syncthreads();
        for (int st = 128; st >= 1; st >>= 1) {
            if (t < st) red[t] += red[t + st];
            __syncthreads();
        }
        if (t == 0) out[b * 10 + k] = red[0] + dec_b[k];
        __syncthreads();
    }
}

extern "C" void kernel_launch(void* const* d_in, const int* in_sizes, int n_in,
                              void* d_out, int out_size) {
    const float* x          = (const float*)d_in[0];
    const float* enc_w      = (const float*)d_in[1];
    const float* enc_b      = (const float*)d_in[2];
    const float* log_dt     = (const float*)d_in[3];
    const float* log_A_real = (const float*)d_in[4];
    const float* A_imag     = (const float*)d_in[5];
    const float* C_re       = (const float*)d_in[6];
    const float* C_im       = (const float*)d_in[7];
    const float* Dvec       = (const float*)d_in[8];
    const float* ln_g       = (const float*)d_in[9];
    const float* ln_b       = (const float*)d_in[10];
    const float* fn_g       = (const float*)d_in[11];
    const float* fn_b       = (const float*)d_in[12];
    const float* dec_w      = (const float*)d_in[13];
    const float* dec_b      = (const float*)d_in[14];
    float* out = (float*)d_out;

    int np = NLAYERS * HDIM * NSTATE;
    precompute_kernel<<<(np + 255) / 256, 256>>>(log_dt, log_A_real, A_imag, C_re, C_im);
    kgen_kernel<<<dim3(HDIM / 16, NLAYERS), 128>>>();
    krr_kernel<<<dim3(HDIM, NLAYERS), 256>>>(Dvec);
    encoder_kernel<<<LSEQ, 256>>>(x, enc_w, enc_b);

    for (int i = 0; i < NLAYERS; i++) {
        gemm_kernel<<<HDIM * MT, 256>>>(i);
        int last = (i == NLAYERS - 1);
        ln_kernel<<<LSEQ, 512>>>(ln_g + i * HDIM, ln_b + i * HDIM, 1, last, !last);
    }
    ln_kernel<<<LSEQ, 512>>>(fn_g, fn_b, 0, 1, 0);
    pool_kernel<<<HDIM, 256>>>();
    decode_kernel<<<BATCH, 256>>>(dec_w, dec_b, out);
}

// round 15
// speedup vs baseline: 2.8465x; 1.3181x over previous
#include <cuda_runtime.h>
#include <cuda_fp16.h>
#include <cuda_bf16.h>
#include <cstddef>
#include <cstdint>

#define BATCH 64
#define LSEQ 784
#define HDIM 512
#define NSTATE 64
#define NLAYERS 6
#define MT 7             // m-tiles of 128 rows, 7*128 = 896 >= 784
#define REV 895
#define KRRN 1024        // reversed-padded kernel length per h

// -------- scratch (no allocations allowed) --------
__device__ float g_h[(size_t)HDIM * LSEQ * BATCH];   // fp32 activations (only last 2 LNs)
__device__ float g_y[(size_t)HDIM * LSEQ * BATCH];   // z = h + conv(h), (H,L,B)
__device__ __half g_uf[(size_t)HDIM * LSEQ * BATCH]; // fp16 activations for gemm B operand
__device__ float g_K[NLAYERS * HDIM * LSEQ];         // conv kernels (fp32)
__device__ __half g_krh[(size_t)NLAYERS * HDIM * KRRN];  // K' reversed, fp16 hi
__device__ __half g_krl[(size_t)NLAYERS * HDIM * KRRN];  // K' reversed, fp16 lo
__device__ float g_wr[NLAYERS * HDIM * NSTATE];
__device__ float g_wi[NLAYERS * HDIM * NSTATE];
__device__ float g_cr[NLAYERS * HDIM * NSTATE];
__device__ float g_ci[NLAYERS * HDIM * NSTATE];
__device__ float g_pool[HDIM * BATCH];

// -------- ptx helpers --------
__device__ __forceinline__ uint32_t smaddr(const void* p) {
    return (uint32_t)__cvta_generic_to_shared(p);
}
__device__ __forceinline__ void ldsm4t(uint32_t& r0, uint32_t& r1, uint32_t& r2, uint32_t& r3,
                                       uint32_t addr) {
    asm volatile("ldmatrix.sync.aligned.m8n8.x4.trans.shared.b16 {%0,%1,%2,%3}, [%4];"
                 : "=r"(r0), "=r"(r1), "=r"(r2), "=r"(r3) : "r"(addr));
}
__device__ __forceinline__ void mma16816h(float* d, uint32_t a0, uint32_t a1, uint32_t a2,
                                          uint32_t a3, uint32_t b0, uint32_t b1) {
    asm volatile("mma.sync.aligned.m16n8k16.row.col.f32.f16.f16.f32 "
                 "{%0,%1,%2,%3}, {%4,%5,%6,%7}, {%8,%9}, {%0,%1,%2,%3};"
                 : "+f"(d[0]), "+f"(d[1]), "+f"(d[2]), "+f"(d[3])
                 : "r"(a0), "r"(a1), "r"(a2), "r"(a3), "r"(b0), "r"(b1));
}
__device__ __forceinline__ void cpasync16(uint32_t dst, const void* src, int sz) {
    asm volatile("cp.async.cg.shared.global [%0], [%1], 16, %2;"
                 :: "r"(dst), "l"(src), "r"(sz));
}

// -------- precompute discretized SSM params --------
__global__ void precompute_kernel(const float* __restrict__ log_dt,
                                  const float* __restrict__ log_A_real,
                                  const float* __restrict__ A_imag,
                                  const float* __restrict__ C_re,
                                  const float* __restrict__ C_im) {
    int idx = blockIdx.x * blockDim.x + threadIdx.x;
    if (idx >= NLAYERS * HDIM * NSTATE) return;
    int hh = (idx / NSTATE) % HDIM;
    int i = idx / (NSTATE * HDIM);
    float dt = expf(log_dt[i * HDIM + hh]);
    float Ar = -expf(log_A_real[idx]);
    float Ai = A_imag[idx];
    float xr = Ar * dt, xi = Ai * dt;
    float e = expf(xr);
    float wre = e * cosf(xi), wim = e * sinf(xi);
    float em1r = wre - 1.0f, em1i = wim;
    float Cre = C_re[idx], Cim = C_im[idx];
    float tr = Cre * em1r - Cim * em1i;
    float ti = Cre * em1i + Cim * em1r;
    float inv = 1.0f / (Ar * Ar + Ai * Ai);
    g_wr[idx] = wre; g_wi[idx] = wim;
    g_cr[idx] = (tr * Ar + ti * Ai) * inv;
    g_ci[idx] = (ti * Ar - tr * Ai) * inv;
}

// -------- kernel generation: impulse response of the recurrence --------
__global__ void __launch_bounds__(128) kgen_kernel() {
    __shared__ float shy[16][120];
    int tid = threadIdx.x;
    int warp = tid >> 5, lane = tid & 31;
    int g = lane >> 3, lg = lane & 7;
    int pairLocal = warp * 4 + g;
    int h = blockIdx.x * 16 + pairLocal;
    int layer = blockIdx.y;
    int pbase = (layer * HDIM + h) * NSTATE;
    float swr[8], swi[8], scr[8], sci[8], sre[8], sim[8];
#pragma unroll
    for (int j = 0; j < 8; j++) {
        int n = lg + 8 * j;
        swr[j] = g_wr[pbase + n]; swi[j] = g_wi[pbase + n];
        scr[j] = g_cr[pbase + n]; sci[j] = g_ci[pbase + n];
        sre[j] = 0.0f; sim[j] = 0.0f;
    }
    float* krow = g_K + (size_t)(layer * HDIM + h) * LSEQ;
    for (int c0 = 0; c0 < LSEQ; c0 += 112) {
#pragma unroll 4
        for (int l = 0; l < 112; l++) {
            float uv = (c0 + l == 0) ? 1.0f : 0.0f;
            float acc = 0.0f;
#pragma unroll
            for (int j = 0; j < 8; j++) {
                float nr = fmaf(swr[j], sre[j], fmaf(-swi[j], sim[j], uv));
                float ni = fmaf(swr[j], sim[j], swi[j] * sre[j]);
                sre[j] = nr; sim[j] = ni;
                acc = fmaf(scr[j], nr, acc);
                acc = fmaf(-sci[j], ni, acc);
            }
            acc += __shfl_xor_sync(0xffffffffu, acc, 1, 8);
            acc += __shfl_xor_sync(0xffffffffu, acc, 2, 8);
            acc += __shfl_xor_sync(0xffffffffu, acc, 4, 8);
            if (lg == 0) shy[pairLocal][l] = 2.0f * acc;
        }
        __syncwarp();
#pragma unroll
        for (int k = 0; k < 14; k++)
            krow[c0 + lg + 8 * k] = shy[pairLocal][lg + 8 * k];
        __syncwarp();
    }
}

// -------- build reversed zero-padded fp16 hi/lo kernel, residual folded in --------
// KRR[t] = Kpad[REV - t]; K'[0] = K[0] + 1 + D  (so z = Sum K'[d] u[t-d] directly)
__global__ void __launch_bounds__(256) krr_kernel(const float* __restrict__ Dvec) {
    int h = blockIdx.x, layer = blockIdx.y;
    const float* kr = g_K + (size_t)(layer * HDIM + h) * LSEQ;
    __half* oh = g_krh + (size_t)(layer * HDIM + h) * KRRN;
    __half* ol = g_krl + (size_t)(layer * HDIM + h) * KRRN;
    float Dadd = 1.0f + Dvec[layer * HDIM + h];
    for (int t = threadIdx.x; t < KRRN; t += 256) {
        int d = REV - t;
        float v = (d >= 0 && d < LSEQ) ? kr[d] : 0.0f;
        if (d == 0) v += Dadd;
        __half hi = __float2half_rn(v);
        oh[t] = hi;
        ol[t] = __float2half_rn(v - __half2float(hi));
    }
}

// -------- encoder: fp16 activations only --------
__global__ void __launch_bounds__(256) encoder_kernel(const float* __restrict__ x,
                                                      const float* __restrict__ enc_w,
                                                      const float* __restrict__ enc_b) {
    int l = blockIdx.x;
    __shared__ float xs[BATCH];
    if (threadIdx.x < BATCH) xs[threadIdx.x] = x[threadIdx.x * LSEQ + l];
    __syncthreads();
    for (int idx = threadIdx.x; idx < HDIM * BATCH; idx += 256) {
        int h = idx >> 6, b = idx & 63;
        size_t off = ((size_t)h * LSEQ + l) * BATCH + b;
        float v = fmaf(xs[b], enc_w[h], enc_b[h]);
        g_uf[off] = __float2half_rn(v);
    }
}

// -------- S4 conv as triangular Toeplitz GEMM (fp16, K hi/lo split) --------
// 256 threads / 8 warps. Block: (h, 128-row m-tile). k-chunks of 32.
// B (U, single fp16 plane) staged by cp.async, 3-stage pipeline, swizzle unit^=(k&7).
// A fragments from dual-shift pair tables: 1 aligned LDS.32 each.
__global__ void __launch_bounds__(256) gemm_kernel(int layer) {
    __shared__ __align__(16) __half Kraw[2][KRRN];             // 4KB
    __shared__ uint32_t Kpair[2][2][KRRN / 2];                 // 8KB [plane][shift][i]
    __shared__ __align__(16) uint8_t Usm[3][32 * 128];         // 12KB [buf]
    int tid = threadIdx.x;
    int id = blockIdx.x;
    int mt = MT - 1 - (id % MT);   // big-work-first scheduling
    int h = id / MT;
    int m0 = mt * 128;
    int warp = tid >> 5, lane = tid & 31;
    int g = lane >> 2, t2 = (lane & 3) * 2;

    {   // load kernel slice (hi+lo) vectorized: 2 planes x 1024 halves = 256 uint4
        const uint4* kh4 = (const uint4*)(g_krh + (size_t)(layer * HDIM + h) * KRRN);
        const uint4* kl4 = (const uint4*)(g_krl + (size_t)(layer * HDIM + h) * KRRN);
        int p = tid >> 7, j = tid & 127;
        ((uint4*)Kraw[p])[j] = p ? kl4[j] : kh4[j];
    }
    __syncthreads();
    {   // build dual-shift pair tables: Kpair[pl][sh][i] = elem(2i+sh) | elem(2i+sh+1)<<16
        const uint16_t* r0 = (const uint16_t*)Kraw[0];
        const uint16_t* r1 = (const uint16_t*)Kraw[1];
#pragma unroll
        for (int e = tid; e < 2048; e += 256) {
            int pl = e >> 10, rest = e & 1023;
            int sh = rest >> 9, i = rest & 511;
            int x = 2 * i + sh;
            const uint16_t* rr = pl ? r1 : r0;
            uint32_t lo = rr[x];
            uint32_t hi = (x + 1 < KRRN) ? rr[x + 1] : 0u;
            Kpair[pl][sh][i] = lo | (hi << 16);
        }
    }

    // staging: 256 threads, one 16B cp.async per chunk (32 rows x 8 segments)
    const __half* usrc = g_uf + (size_t)h * (LSEQ * BATCH);
    int sk = tid >> 3, sj = tid & 7;             // sk 0..31
    uint32_t doff = (uint32_t)(sk * 128 + ((sj ^ (sk & 7)) << 4));
    uint32_t sbase[3] = { smaddr(&Usm[0][0]) + doff, smaddr(&Usm[1][0]) + doff,
                          smaddr(&Usm[2][0]) + doff };

    int nc = mt * 4 + 4;   // 32-wide chunks cover k < m0+128

    // prologue: issue chunks 0 and 1
    cpasync16(sbase[0], usrc + (size_t)sk * BATCH + sj * 8, 16);
    asm volatile("cp.async.commit_group;");
    {
        int kA = 32 + sk;
        cpasync16(sbase[1], usrc + (size_t)(kA < LSEQ ? kA : 0) * BATCH + sj * 8,
                  (kA < LSEQ) ? 16 : 0);
        asm volatile("cp.async.commit_group;");
    }
    __syncthreads();   // Kpair tables ready before mma loop

    float acc[8][4];
#pragma unroll
    for (int u = 0; u < 8; u++)
#pragma unroll
        for (int c = 0; c < 4; c++) acc[u][c] = 0.0f;

    // ldmatrix.trans lane mapping
    int r = lane & 7, mm = lane >> 3;
    int khh = mm & 1, bg = mm >> 1;
    uint32_t rowoff = (uint32_t)((khh * 8 + r) * 128);

    // A-fragment index base; parity of x is constant per lane across the loop
    int xb = REV - m0 - warp * 16 + t2 - g;
    int par = xb & 1;
    const uint32_t* KPh = Kpair[0][par];
    const uint32_t* KPl = Kpair[1][par];

    int buf = 0;
    for (int kc = 0; kc < nc; kc++) {
        asm volatile("cp.async.wait_group 1;" ::: "memory");
        __syncthreads();
        {   // issue chunk kc+2 into the buffer freed by chunk kc-1
            if (kc + 2 < nc) {
                int nb = buf + 2; if (nb >= 3) nb -= 3;
                int kA = (kc + 2) * 32 + sk;
                cpasync16(sbase[nb], usrc + (size_t)(kA < LSEQ ? kA : 0) * BATCH + sj * 8,
                          (kA < LSEQ) ? 16 : 0);
            }
            asm volatile("cp.async.commit_group;");   // empty group ok at tail
        }
        uint32_t bb = smaddr(&Usm[buf][0]) + rowoff;
#pragma unroll
        for (int kk = 0; kk < 32; kk += 16) {
            int xi = (xb + kc * 32 + kk) >> 1;       // pair index (parity folded into KP*)
            uint32_t ah0 = KPh[xi], ah1 = KPh[xi - 4], ah2 = KPh[xi + 4];
            uint32_t al0 = KPl[xi], al1 = KPl[xi - 4], al2 = KPl[xi + 4];
            uint32_t kof = (uint32_t)(kk * 128);
#pragma unroll
            for (int ng = 0; ng < 4; ng++) {
                uint32_t unit = (uint32_t)(((ng * 2 + bg) ^ r) << 4);
                uint32_t r0, r1, r2, r3;
                ldsm4t(r0, r1, r2, r3, bb + kof + unit);
                mma16816h(acc[2 * ng],     ah0, ah1, ah2, ah0, r0, r1);
                mma16816h(acc[2 * ng],     al0, al1, al2, al0, r0, r1);
                mma16816h(acc[2 * ng + 1], ah0, ah1, ah2, ah0, r2, r3);
                mma16816h(acc[2 * ng + 1], al0, al1, al2, al0, r2, r3);
            }
        }
        buf++; if (buf == 3) buf = 0;
    }

    // epilogue: z = acc (residual + D folded into K'), into g_y (H,L,B)
    float* Z = g_y + (size_t)h * (LSEQ * BATCH);
    int R0 = m0 + warp * 16 + g;
    int R1 = R0 + 8;
#pragma unroll
    for (int u = 0; u < 8; u++) {
        int b = u * 8 + t2;
        if (R0 < LSEQ) {
            size_t o = (size_t)R0 * BATCH + b;
            Z[o] = acc[u][0]; Z[o + 1] = acc[u][1];
        }
        if (R1 < LSEQ) {
            size_t o = (size_t)R1 * BATCH + b;
            Z[o] = acc[u][2]; Z[o + 1] = acc[u][3];
        }
    }
}

// -------- layernorm over H, (H,L,B) layout, coalesced two-pass --------
__global__ void __launch_bounds__(512) ln_kernel(const float* __restrict__ gamma,
                                                 const float* __restrict__ beta,
                                                 int addY, int writeFP, int writeHF) {
    int l = blockIdx.x;
    int t = threadIdx.x;
    int b = t & 63, hp = t >> 6;   // hp 0..7
    const float* src = (addY ? g_y : g_h) + (size_t)l * BATCH;
    float s1 = 0.0f, s2 = 0.0f;
    for (int h = hp; h < HDIM; h += 8) {
        float v = __ldg(src + (size_t)h * (LSEQ * BATCH) + b);
        s1 += v; s2 += v * v;
    }
    __shared__ float r1[8][64], r2[8][64];
    __shared__ float smean[64], srstd[64];
    r1[hp][b] = s1; r2[hp][b] = s2;
    __syncthreads();
    if (t < 64) {
        float a1 = 0.0f, a2 = 0.0f;
#pragma unroll
        for (int i = 0; i < 8; i++) { a1 += r1[i][t]; a2 += r2[i][t]; }
        float mean = a1 * (1.0f / HDIM);
        float var = a2 * (1.0f / HDIM) - mean * mean;
        smean[t] = mean;
        srstd[t] = rsqrtf(var + 1e-5f);
    }
    __syncthreads();
    float mean = smean[b], rstd = srstd[b];
    size_t lb = (size_t)l * BATCH;
    for (int h = hp; h < HDIM; h += 8) {
        size_t off = (size_t)h * (LSEQ * BATCH) + lb + b;
        float v = (__ldg(src + (size_t)h * (LSEQ * BATCH) + b) - mean) * rstd * gamma[h]
                  + beta[h];
        if (writeFP) g_h[off] = v;
        if (writeHF) g_uf[off] = __float2half_rn(v);
    }
}

// -------- mean-pool over L --------
__global__ void __launch_bounds__(256) pool_kernel() {
    int h = blockIdx.x;
    int b = threadIdx.x & 63, part = threadIdx.x >> 6;
    float s = 0.0f;
    for (int l = part; l < LSEQ; l += 4)
        s += g_h[((size_t)h * LSEQ + l) * BATCH + b];
    __shared__ float red[4][64];
    red[part][b] = s;
    __syncthreads();
    if (part == 0)
        g_pool[h * BATCH + b] = (red[0][b] + red[1][b] + red[2][b] + red[3][b]) * (1.0f / LSEQ);
}

// -------- decode to 10 classes --------
__global__ void __launch_bounds__(256) decode_kernel(const float* __restrict__ dec_w,
                                                     const float* __restrict__ dec_b,
                                                     float* __restrict__ out) {
    int b = blockIdx.x;
    int t = threadIdx.x;
    float acc[10];
#pragma unroll
    for (int k = 0; k < 10; k++) acc[k] = 0.0f;
    for (int h = t; h < HDIM; h += 256) {
        float p = g_pool[h * BATCH + b];
#pragma unroll
        for (int k = 0; k < 10; k++) acc[k] = fmaf(p, dec_w[h * 10 + k], acc[k]);
    }
    __shared__ float red[256];
    for (int k = 0; k < 10; k++) {
        red[t] = acc[k];
        __syncthreads();
        for (int st = 128; st >= 1; st >>= 1) {
            if (t < st) red[t] += red[t + st];
            __syncthreads();
        }
        if (t == 0) out[b * 10 + k] = red[0] + dec_b[k];
        __syncthreads();
    }
}

extern "C" void kernel_launch(void* const* d_in, const int* in_sizes, int n_in,
                              void* d_out, int out_size) {
    const float* x          = (const float*)d_in[0];
    const float* enc_w      = (const float*)d_in[1];
    const float* enc_b      = (const float*)d_in[2];
    const float* log_dt     = (const float*)d_in[3];
    const float* log_A_real = (const float*)d_in[4];
    const float* A_imag     = (const float*)d_in[5];
    const float* C_re       = (const float*)d_in[6];
    const float* C_im       = (const float*)d_in[7];
    const float* Dvec       = (const float*)d_in[8];
    const float* ln_g       = (const float*)d_in[9];
    const float* ln_b       = (const float*)d_in[10];
    const float* fn_g       = (const float*)d_in[11];
    const float* fn_b       = (const float*)d_in[12];
    const float* dec_w      = (const float*)d_in[13];
    const float* dec_b      = (const float*)d_in[14];
    float* out = (float*)d_out;

    int np = NLAYERS * HDIM * NSTATE;
    precompute_kernel<<<(np + 255) / 256, 256>>>(log_dt, log_A_real, A_imag, C_re, C_im);
    kgen_kernel<<<dim3(HDIM / 16, NLAYERS), 128>>>();
    krr_kernel<<<dim3(HDIM, NLAYERS), 256>>>(Dvec);
    encoder_kernel<<<LSEQ, 256>>>(x, enc_w, enc_b);

    for (int i = 0; i < NLAYERS; i++) {
        gemm_kernel<<<HDIM * MT, 256>>>(i);
        int last = (i == NLAYERS - 1);
        ln_kernel<<<LSEQ, 512>>>(ln_g + i * HDIM, ln_b + i * HDIM, 1, last, !last);
    }
    ln_kernel<<<LSEQ, 512>>>(fn_g, fn_b, 0, 1, 0);
    pool_kernel<<<HDIM, 256>>>();
    decode_kernel<<<BATCH, 256>>>(dec_w, dec_b, out);
}

// round 16
// speedup vs baseline: 3.0355x; 1.0664x over previous
#include <cuda_runtime.h>
#include <cuda_fp16.h>
#include <cuda_bf16.h>
#include <cstddef>
#include <cstdint>

#define BATCH 64
#define LSEQ 784
#define HDIM 512
#define NSTATE 64
#define NLAYERS 6
#define MT 7             // m-tiles of 128 rows, 7*128 = 896 >= 784
#define REV 895
#define KRRN 1024        // reversed-padded kernel length per h

// -------- scratch (no allocations allowed) --------
__device__ float g_h[(size_t)HDIM * LSEQ * BATCH];   // fp32 activations (only last 2 LNs)
__device__ float g_y[(size_t)HDIM * LSEQ * BATCH];   // z = h + conv(h), (H,L,B)
__device__ __half g_uf[(size_t)HDIM * LSEQ * BATCH]; // fp16 activations for gemm B operand
__device__ float g_K[NLAYERS * HDIM * LSEQ];         // conv kernels (fp32)
__device__ __half g_krh[(size_t)NLAYERS * HDIM * KRRN];  // K' reversed, fp16 hi
__device__ __half g_krl[(size_t)NLAYERS * HDIM * KRRN];  // K' reversed, fp16 lo
__device__ float g_wr[NLAYERS * HDIM * NSTATE];
__device__ float g_wi[NLAYERS * HDIM * NSTATE];
__device__ float g_cr[NLAYERS * HDIM * NSTATE];
__device__ float g_ci[NLAYERS * HDIM * NSTATE];
__device__ float g_pool[HDIM * BATCH];

// -------- ptx helpers --------
__device__ __forceinline__ uint32_t smaddr(const void* p) {
    return (uint32_t)__cvta_generic_to_shared(p);
}
__device__ __forceinline__ void ldsm4t(uint32_t& r0, uint32_t& r1, uint32_t& r2, uint32_t& r3,
                                       uint32_t addr) {
    asm volatile("ldmatrix.sync.aligned.m8n8.x4.trans.shared.b16 {%0,%1,%2,%3}, [%4];"
                 : "=r"(r0), "=r"(r1), "=r"(r2), "=r"(r3) : "r"(addr));
}
__device__ __forceinline__ void mma16816h(float* d, uint32_t a0, uint32_t a1, uint32_t a2,
                                          uint32_t a3, uint32_t b0, uint32_t b1) {
    asm volatile("mma.sync.aligned.m16n8k16.row.col.f32.f16.f16.f32 "
                 "{%0,%1,%2,%3}, {%4,%5,%6,%7}, {%8,%9}, {%0,%1,%2,%3};"
                 : "+f"(d[0]), "+f"(d[1]), "+f"(d[2]), "+f"(d[3])
                 : "r"(a0), "r"(a1), "r"(a2), "r"(a3), "r"(b0), "r"(b1));
}
__device__ __forceinline__ void cpasync16(uint32_t dst, const void* src, int sz) {
    asm volatile("cp.async.cg.shared.global [%0], [%1], 16, %2;"
                 :: "r"(dst), "l"(src), "r"(sz));
}

// -------- precompute discretized SSM params --------
__global__ void precompute_kernel(const float* __restrict__ log_dt,
                                  const float* __restrict__ log_A_real,
                                  const float* __restrict__ A_imag,
                                  const float* __restrict__ C_re,
                                  const float* __restrict__ C_im) {
    int idx = blockIdx.x * blockDim.x + threadIdx.x;
    if (idx >= NLAYERS * HDIM * NSTATE) return;
    int hh = (idx / NSTATE) % HDIM;
    int i = idx / (NSTATE * HDIM);
    float dt = expf(log_dt[i * HDIM + hh]);
    float Ar = -expf(log_A_real[idx]);
    float Ai = A_imag[idx];
    float xr = Ar * dt, xi = Ai * dt;
    float e = expf(xr);
    float wre = e * cosf(xi), wim = e * sinf(xi);
    float em1r = wre - 1.0f, em1i = wim;
    float Cre = C_re[idx], Cim = C_im[idx];
    float tr = Cre * em1r - Cim * em1i;
    float ti = Cre * em1i + Cim * em1r;
    float inv = 1.0f / (Ar * Ar + Ai * Ai);
    g_wr[idx] = wre; g_wi[idx] = wim;
    g_cr[idx] = (tr * Ar + ti * Ai) * inv;
    g_ci[idx] = (ti * Ar - tr * Ai) * inv;
}

// -------- kernel generation: impulse response of the recurrence --------
__global__ void __launch_bounds__(128) kgen_kernel() {
    __shared__ float shy[16][120];
    int tid = threadIdx.x;
    int warp = tid >> 5, lane = tid & 31;
    int g = lane >> 3, lg = lane & 7;
    int pairLocal = warp * 4 + g;
    int h = blockIdx.x * 16 + pairLocal;
    int layer = blockIdx.y;
    int pbase = (layer * HDIM + h) * NSTATE;
    float swr[8], swi[8], scr[8], sci[8], sre[8], sim[8];
#pragma unroll
    for (int j = 0; j < 8; j++) {
        int n = lg + 8 * j;
        swr[j] = g_wr[pbase + n]; swi[j] = g_wi[pbase + n];
        scr[j] = g_cr[pbase + n]; sci[j] = g_ci[pbase + n];
        sre[j] = 0.0f; sim[j] = 0.0f;
    }
    float* krow = g_K + (size_t)(layer * HDIM + h) * LSEQ;
    for (int c0 = 0; c0 < LSEQ; c0 += 112) {
#pragma unroll 4
        for (int l = 0; l < 112; l++) {
            float uv = (c0 + l == 0) ? 1.0f : 0.0f;
            float acc = 0.0f;
#pragma unroll
            for (int j = 0; j < 8; j++) {
                float nr = fmaf(swr[j], sre[j], fmaf(-swi[j], sim[j], uv));
                float ni = fmaf(swr[j], sim[j], swi[j] * sre[j]);
                sre[j] = nr; sim[j] = ni;
                acc = fmaf(scr[j], nr, acc);
                acc = fmaf(-sci[j], ni, acc);
            }
            acc += __shfl_xor_sync(0xffffffffu, acc, 1, 8);
            acc += __shfl_xor_sync(0xffffffffu, acc, 2, 8);
            acc += __shfl_xor_sync(0xffffffffu, acc, 4, 8);
            if (lg == 0) shy[pairLocal][l] = 2.0f * acc;
        }
        __syncwarp();
#pragma unroll
        for (int k = 0; k < 14; k++)
            krow[c0 + lg + 8 * k] = shy[pairLocal][lg + 8 * k];
        __syncwarp();
    }
}

// -------- build reversed zero-padded fp16 hi/lo kernel, residual folded in --------
// KRR[t] = Kpad[REV - t]; K'[0] = K[0] + 1 + D  (so z = Sum K'[d] u[t-d] directly)
__global__ void __launch_bounds__(256) krr_kernel(const float* __restrict__ Dvec) {
    int h = blockIdx.x, layer = blockIdx.y;
    const float* kr = g_K + (size_t)(layer * HDIM + h) * LSEQ;
    __half* oh = g_krh + (size_t)(layer * HDIM + h) * KRRN;
    __half* ol = g_krl + (size_t)(layer * HDIM + h) * KRRN;
    float Dadd = 1.0f + Dvec[layer * HDIM + h];
    for (int t = threadIdx.x; t < KRRN; t += 256) {
        int d = REV - t;
        float v = (d >= 0 && d < LSEQ) ? kr[d] : 0.0f;
        if (d == 0) v += Dadd;
        __half hi = __float2half_rn(v);
        oh[t] = hi;
        ol[t] = __float2half_rn(v - __half2float(hi));
    }
}

// -------- encoder: fp16 activations only --------
__global__ void __launch_bounds__(256) encoder_kernel(const float* __restrict__ x,
                                                      const float* __restrict__ enc_w,
                                                      const float* __restrict__ enc_b) {
    int l = blockIdx.x;
    __shared__ float xs[BATCH];
    if (threadIdx.x < BATCH) xs[threadIdx.x] = x[threadIdx.x * LSEQ + l];
    __syncthreads();
    for (int idx = threadIdx.x; idx < HDIM * BATCH; idx += 256) {
        int h = idx >> 6, b = idx & 63;
        size_t off = ((size_t)h * LSEQ + l) * BATCH + b;
        float v = fmaf(xs[b], enc_w[h], enc_b[h]);
        g_uf[off] = __float2half_rn(v);
    }
}

// -------- S4 conv as triangular Toeplitz GEMM (fp16, K hi/lo split) --------
// 256 threads / 8 warps. Block: (h, 128-row m-tile). k-chunks of 64 (fewer barriers).
// B (U, single fp16 plane) staged by cp.async, 3-stage pipeline, swizzle unit^=(k&7).
// Per-warp triangular skip: a warp skips ldsm+mma for k16 groups entirely above its rows.
__global__ void __launch_bounds__(256) gemm_kernel(int layer) {
    __shared__ __align__(16) __half Kraw[2][KRRN];             // 4KB
    __shared__ uint32_t Kpair[2][2][KRRN / 2];                 // 8KB [plane][shift][i]
    __shared__ __align__(16) uint8_t Usm[3][64 * 128];         // 24KB [buf]
    int tid = threadIdx.x;
    int id = blockIdx.x;
    int mt = MT - 1 - (id % MT);   // big-work-first scheduling
    int h = id / MT;
    int m0 = mt * 128;
    int warp = tid >> 5, lane = tid & 31;
    int g = lane >> 2, t2 = (lane & 3) * 2;

    {   // load kernel slice (hi+lo) vectorized: 2 planes x 1024 halves = 256 uint4
        const uint4* kh4 = (const uint4*)(g_krh + (size_t)(layer * HDIM + h) * KRRN);
        const uint4* kl4 = (const uint4*)(g_krl + (size_t)(layer * HDIM + h) * KRRN);
        int p = tid >> 7, j = tid & 127;
        ((uint4*)Kraw[p])[j] = p ? kl4[j] : kh4[j];
    }
    __syncthreads();
    {   // build dual-shift pair tables: Kpair[pl][sh][i] = elem(2i+sh) | elem(2i+sh+1)<<16
        const uint16_t* r0 = (const uint16_t*)Kraw[0];
        const uint16_t* r1 = (const uint16_t*)Kraw[1];
#pragma unroll
        for (int e = tid; e < 2048; e += 256) {
            int pl = e >> 10, rest = e & 1023;
            int sh = rest >> 9, i = rest & 511;
            int x = 2 * i + sh;
            const uint16_t* rr = pl ? r1 : r0;
            uint32_t lo = rr[x];
            uint32_t hi = (x + 1 < KRRN) ? rr[x + 1] : 0u;
            Kpair[pl][sh][i] = lo | (hi << 16);
        }
    }

    // staging: 256 threads, two 16B cp.async per 64-row chunk (rows sk, sk+32)
    const __half* usrc = g_uf + (size_t)h * (LSEQ * BATCH);
    int sk = tid >> 3, sj = tid & 7;             // sk 0..31; second row = sk+32
    uint32_t doffA = (uint32_t)(sk * 128 + ((sj ^ (sk & 7)) << 4));
    uint32_t doffB = (uint32_t)((sk + 32) * 128 + ((sj ^ ((sk + 32) & 7)) << 4));
    uint32_t sb0 = smaddr(&Usm[0][0]), sb1 = smaddr(&Usm[1][0]), sb2 = smaddr(&Usm[2][0]);

    int nc = mt * 2 + 2;   // 64-wide chunks cover k < m0+128

    // prologue: issue chunks 0 and 1 (chunk 0 rows always < 784)
    cpasync16(sb0 + doffA, usrc + (size_t)sk * BATCH + sj * 8, 16);
    cpasync16(sb0 + doffB, usrc + (size_t)(sk + 32) * BATCH + sj * 8, 16);
    asm volatile("cp.async.commit_group;");
    {
        int kA = 64 + sk, kB = 64 + sk + 32;
        cpasync16(sb1 + doffA, usrc + (size_t)(kA < LSEQ ? kA : 0) * BATCH + sj * 8,
                  (kA < LSEQ) ? 16 : 0);
        cpasync16(sb1 + doffB, usrc + (size_t)(kB < LSEQ ? kB : 0) * BATCH + sj * 8,
                  (kB < LSEQ) ? 16 : 0);
        asm volatile("cp.async.commit_group;");
    }
    __syncthreads();   // Kpair tables ready before mma loop

    float acc[8][4];
#pragma unroll
    for (int u = 0; u < 8; u++)
#pragma unroll
        for (int c = 0; c < 4; c++) acc[u][c] = 0.0f;

    // ldmatrix.trans lane mapping
    int r = lane & 7, mm = lane >> 3;
    int khh = mm & 1, bg = mm >> 1;
    uint32_t rowoff = (uint32_t)((khh * 8 + r) * 128);

    // A-fragment index base; parity of x is constant per lane across the loop
    int xb = REV - m0 - warp * 16 + t2 - g;
    int par = xb & 1;
    const uint32_t* KPh = Kpair[0][par];
    const uint32_t* KPl = Kpair[1][par];
    int wmax = m0 + warp * 16 + 15;   // triangular skip bound for this warp

    uint32_t sbase[3] = { sb0, sb1, sb2 };
    int buf = 0;
    for (int kc = 0; kc < nc; kc++) {
        asm volatile("cp.async.wait_group 1;" ::: "memory");
        __syncthreads();
        {   // issue chunk kc+2 into the buffer freed by chunk kc-1
            if (kc + 2 < nc) {
                int nb = buf + 2; if (nb >= 3) nb -= 3;
                int kA = (kc + 2) * 64 + sk, kB = kA + 32;
                cpasync16(sbase[nb] + doffA,
                          usrc + (size_t)(kA < LSEQ ? kA : 0) * BATCH + sj * 8,
                          (kA < LSEQ) ? 16 : 0);
                cpasync16(sbase[nb] + doffB,
                          usrc + (size_t)(kB < LSEQ ? kB : 0) * BATCH + sj * 8,
                          (kB < LSEQ) ? 16 : 0);
            }
            asm volatile("cp.async.commit_group;");   // empty group ok at tail
        }
        uint32_t bb = sbase[buf] + rowoff;
#pragma unroll
        for (int kk = 0; kk < 64; kk += 16) {
            int kabs = kc * 64 + kk;
            if (kabs > wmax) break;                  // A all-zero above the diagonal
            int xi = (xb + kabs) >> 1;               // pair index (parity folded into KP*)
            uint32_t ah0 = KPh[xi], ah1 = KPh[xi - 4], ah2 = KPh[xi + 4];
            uint32_t al0 = KPl[xi], al1 = KPl[xi - 4], al2 = KPl[xi + 4];
            uint32_t kof = (uint32_t)(kk * 128);
#pragma unroll
            for (int ng = 0; ng < 4; ng++) {
                uint32_t unit = (uint32_t)(((ng * 2 + bg) ^ r) << 4);
                uint32_t r0, r1, r2, r3;
                ldsm4t(r0, r1, r2, r3, bb + kof + unit);
                mma16816h(acc[2 * ng],     ah0, ah1, ah2, ah0, r0, r1);
                mma16816h(acc[2 * ng],     al0, al1, al2, al0, r0, r1);
                mma16816h(acc[2 * ng + 1], ah0, ah1, ah2, ah0, r2, r3);
                mma16816h(acc[2 * ng + 1], al0, al1, al2, al0, r2, r3);
            }
        }
        buf++; if (buf == 3) buf = 0;
    }

    // epilogue: z = acc (residual + D folded into K'), into g_y (H,L,B)
    float* Z = g_y + (size_t)h * (LSEQ * BATCH);
    int R0 = m0 + warp * 16 + g;
    int R1 = R0 + 8;
#pragma unroll
    for (int u = 0; u < 8; u++) {
        int b = u * 8 + t2;
        if (R0 < LSEQ) {
            size_t o = (size_t)R0 * BATCH + b;
            Z[o] = acc[u][0]; Z[o + 1] = acc[u][1];
        }
        if (R1 < LSEQ) {
            size_t o = (size_t)R1 * BATCH + b;
            Z[o] = acc[u][2]; Z[o + 1] = acc[u][3];
        }
    }
}

// -------- layernorm over H, (H,L,B) layout, coalesced two-pass --------
__global__ void __launch_bounds__(512) ln_kernel(const float* __restrict__ gamma,
                                                 const float* __restrict__ beta,
                                                 int addY, int writeFP, int writeHF) {
    int l = blockIdx.x;
    int t = threadIdx.x;
    int b = t & 63, hp = t >> 6;   // hp 0..7
    const float* src = (addY ? g_y : g_h) + (size_t)l * BATCH;
    float s1 = 0.0f, s2 = 0.0f;
    for (int h = hp; h < HDIM; h += 8) {
        float v = __ldg(src + (size_t)h * (LSEQ * BATCH) + b);
        s1 += v; s2 += v * v;
    }
    __shared__ float r1[8][64], r2[8][64];
    __shared__ float smean[64], srstd[64];
    r1[hp][b] = s1; r2[hp][b] = s2;
    __syncthreads();
    if (t < 64) {
        float a1 = 0.0f, a2 = 0.0f;
#pragma unroll
        for (int i = 0; i < 8; i++) { a1 += r1[i][t]; a2 += r2[i][t]; }
        float mean = a1 * (1.0f / HDIM);
        float var = a2 * (1.0f / HDIM) - mean * mean;
        smean[t] = mean;
        srstd[t] = rsqrtf(var + 1e-5f);
    }
    __syncthreads();
    float mean = smean[b], rstd = srstd[b];
    size_t lb = (size_t)l * BATCH;
    for (int h = hp; h < HDIM; h += 8) {
        size_t off = (size_t)h * (LSEQ * BATCH) + lb + b;
        float v = (__ldg(src + (size_t)h * (LSEQ * BATCH) + b) - mean) * rstd * gamma[h]
                  + beta[h];
        if (writeFP) g_h[off] = v;
        if (writeHF) g_uf[off] = __float2half_rn(v);
    }
}

// -------- mean-pool over L --------
__global__ void __launch_bounds__(256) pool_kernel() {
    int h = blockIdx.x;
    int b = threadIdx.x & 63, part = threadIdx.x >> 6;
    float s = 0.0f;
    for (int l = part; l < LSEQ; l += 4)
        s += g_h[((size_t)h * LSEQ + l) * BATCH + b];
    __shared__ float red[4][64];
    red[part][b] = s;
    __syncthreads();
    if (part == 0)
        g_pool[h * BATCH + b] = (red[0][b] + red[1][b] + red[2][b] + red[3][b]) * (1.0f / LSEQ);
}

// -------- decode to 10 classes --------
__global__ void __launch_bounds__(256) decode_kernel(const float* __restrict__ dec_w,
                                                     const float* __restrict__ dec_b,
                                                     float* __restrict__ out) {
    int b = blockIdx.x;
    int t = threadIdx.x;
    float acc[10];
#pragma unroll
    for (int k = 0; k < 10; k++) acc[k] = 0.0f;
    for (int h = t; h < HDIM; h += 256) {
        float p = g_pool[h * BATCH + b];
#pragma unroll
        for (int k = 0; k < 10; k++) acc[k] = fmaf(p, dec_w[h * 10 + k], acc[k]);
    }
    __shared__ float red[256];
    for (int k = 0; k < 10; k++) {
        red[t] = acc[k];
        __syncthreads();
        for (int st = 128; st >= 1; st >>= 1) {
            if (t < st) red[t] += red[t + st];
            __syncthreads();
        }
        if (t == 0) out[b * 10 + k] = red[0] + dec_b[k];
        __syncthreads();
    }
}

extern "C" void kernel_launch(void* const* d_in, const int* in_sizes, int n_in,
                              void* d_out, int out_size) {
    const float* x          = (const float*)d_in[0];
    const float* enc_w      = (const float*)d_in[1];
    const float* enc_b      = (const float*)d_in[2];
    const float* log_dt     = (const float*)d_in[3];
    const float* log_A_real = (const float*)d_in[4];
    const float* A_imag     = (const float*)d_in[5];
    const float* C_re       = (const float*)d_in[6];
    const float* C_im       = (const float*)d_in[7];
    const float* Dvec       = (const float*)d_in[8];
    const float* ln_g       = (const float*)d_in[9];
    const float* ln_b       = (const float*)d_in[10];
    const float* fn_g       = (const float*)d_in[11];
    const float* fn_b       = (const float*)d_in[12];
    const float* dec_w      = (const float*)d_in[13];
    const float* dec_b      = (const float*)d_in[14];
    float* out = (float*)d_out;

    int np = NLAYERS * HDIM * NSTATE;
    precompute_kernel<<<(np + 255) / 256, 256>>>(log_dt, log_A_real, A_imag, C_re, C_im);
    kgen_kernel<<<dim3(HDIM / 16, NLAYERS), 128>>>();
    krr_kernel<<<dim3(HDIM, NLAYERS), 256>>>(Dvec);
    encoder_kernel<<<LSEQ, 256>>>(x, enc_w, enc_b);

    for (int i = 0; i < NLAYERS; i++) {
        gemm_kernel<<<HDIM * MT, 256>>>(i);
        int last = (i == NLAYERS - 1);
        ln_kernel<<<LSEQ, 512>>>(ln_g + i * HDIM, ln_b + i * HDIM, 1, last, !last);
    }
    ln_kernel<<<LSEQ, 512>>>(fn_g, fn_b, 0, 1, 0);
    pool_kernel<<<HDIM, 256>>>();
    decode_kernel<<<BATCH, 256>>>(dec_w, dec_b, out);
}